// round 13
// baseline (speedup 1.0000x reference)
#include <cuda_runtime.h>
#include <cuda_fp16.h>
#include <float.h>
#include <math.h>
#include <stdint.h>

#define NWIN 30000
#define NEX  30000
#define EDG  480000
#define HDIM 512
#define NLAYERS 4
#define KWIN 1949
#define KEXP 100
#define NOUT 100
#define MP   30080
#define KP_WIN 1984

// ================= small fp32 scratch =================
__device__ float g_score[NEX];
__device__ float g_bsum[NLAYERS*HDIM];
__device__ __align__(256) float g_lin0[NWIN*NOUT];
__device__ __align__(256) float g_lin1[NEX*NOUT];

// ================= CSR scratch =================
__device__ int g_cnt[3*NWIN];
__device__ int g_off[3*(NWIN+1)];
__device__ int g_cur[3*NWIN];
__device__ int g_csrc[3*EDG];

// ================= fp16 weight buffers [N][Kp] =================
#define WOFF_STEP   (HDIM*HDIM)
#define WOFF_LAYER  (5*WOFF_STEP)
#define WOFF_WLN(l) ((l)*WOFF_LAYER + 0*WOFF_STEP)
#define WOFF_WLR(l) ((l)*WOFF_LAYER + 1*WOFF_STEP)
#define WOFF_WSUM(l)((l)*WOFF_LAYER + 2*WOFF_STEP)
#define WOFF_WLC(l) ((l)*WOFF_LAYER + 3*WOFF_STEP)
#define WOFF_WRC(l) ((l)*WOFF_LAYER + 4*WOFF_STEP)
#define WOFF_POST   (NLAYERS*WOFF_LAYER)
#define WOFF_WIN    (WOFF_POST + WOFF_STEP)
#define WOFF_EXP    (WOFF_WIN + HDIM*KP_WIN)
#define WOFF_LIN    (WOFF_EXP + HDIM*128)
#define WTOTAL      (WOFF_LIN + 128*HDIM)
__device__ __align__(256) __half g_wt[WTOTAL];

// ================= fp16 activation plane buffers =================
__device__ __align__(256) __half g_big[(size_t)MP*KP_WIN];
__device__ __align__(256) __half g_pt[(size_t)MP*HDIM];
__device__ __align__(256) __half g_phw0[(size_t)MP*HDIM];
__device__ __align__(256) __half g_phw1[(size_t)MP*HDIM];
__device__ __align__(256) __half g_phe0[(size_t)MP*HDIM];
__device__ __align__(256) __half g_phe1[(size_t)MP*HDIM];
__device__ __align__(256) __half g_pa0[(size_t)MP*HDIM];
__device__ __align__(256) __half g_pa1[(size_t)MP*HDIM];
__device__ __align__(256) __half g_pa2[(size_t)MP*HDIM];

// ================= batched HxH weight conversion =================
#define NBATCH 21
struct ConvBatch {
    const float* W1[NBATCH];
    const float* W2[NBATCH];
    int dstoff[NBATCH];
};

__global__ void conv_w_batch(const __grid_constant__ ConvBatch cb,
                             __half* __restrict__ ob)
{
    __shared__ float t[32][33];
    int z = blockIdx.z;
    const float* W = cb.W1[z];
    const float* W2 = cb.W2[z];
    __half* o = ob + cb.dstoff[z];
    int k0 = blockIdx.x * 32, n0 = blockIdx.y * 32;
    int tx = threadIdx.x, ty = threadIdx.y;
#pragma unroll
    for (int i = 0; i < 4; i++) {
        int k = k0 + ty + i * 8, n = n0 + tx;
        float v = W[(size_t)k * HDIM + n];
        if (W2) v += W2[(size_t)k * HDIM + n];
        t[ty + i * 8][tx] = v;
    }
    __syncthreads();
#pragma unroll
    for (int i = 0; i < 4; i++) {
        int n = n0 + ty + i * 8, k = k0 + tx;
        o[(size_t)n * HDIM + k] = __float2half_rn(t[tx][ty + i * 8]);
    }
}

__global__ void conv_w(const float* __restrict__ W, int K, int N, int Kp,
                       __half* __restrict__ o)
{
    __shared__ float t[32][33];
    int k0 = blockIdx.x * 32, n0 = blockIdx.y * 32;
    int tx = threadIdx.x, ty = threadIdx.y;
#pragma unroll
    for (int i = 0; i < 4; i++) {
        int k = k0 + ty + i * 8, n = n0 + tx;
        float v = 0.f;
        if (k < K && n < N) v = W[(size_t)k * N + n];
        t[ty + i * 8][tx] = v;
    }
    __syncthreads();
#pragma unroll
    for (int i = 0; i < 4; i++) {
        int n = n0 + ty + i * 8, k = k0 + tx;
        o[(size_t)n * Kp + k] = __float2half_rn(t[tx][ty + i * 8]);
    }
}

__global__ void conv_a(const float* __restrict__ A, int M, int K, int Kp, long long total,
                       __half* __restrict__ o)
{
    long long i = (long long)blockIdx.x * blockDim.x + threadIdx.x;
    if (i >= total) return;
    int m = (int)(i / Kp);
    int k = (int)(i % Kp);
    float v = 0.f;
    if (m < M && k < K) v = A[(size_t)m * K + k];
    o[i] = __float2half_rn(v);
}

__global__ void bias_sum_all(const float* a, const float* b, float* o)
{
    int i = blockIdx.x * blockDim.x + threadIdx.x;
    if (i < NLAYERS * HDIM) o[i] = a[i] + b[i];
}

__global__ void zero_int(int* p, int n)
{
    int i = blockIdx.x * blockDim.x + threadIdx.x;
    if (i < n) p[i] = 0;
}

// ================= CSR build =================
struct EdgePtrs { const int* es[3]; const int* ed[3]; };

__global__ void hist_all(const __grid_constant__ EdgePtrs ep, int* __restrict__ cnt)
{
    int r = blockIdx.y;
    int e = blockIdx.x * blockDim.x + threadIdx.x;
    if (e < EDG) atomicAdd(&cnt[r * NWIN + ep.ed[r][e]], 1);
}

__global__ void scan_all(const int* __restrict__ cnt, int* __restrict__ off,
                         int* __restrict__ cur)
{
    __shared__ int s[1024];
    int r = blockIdx.x;
    const int* c = cnt + r * NWIN;
    int* of = off + r * (NWIN + 1);
    int* cu = cur + r * NWIN;
    int t = threadIdx.x;
    int chunk = (NWIN + 1023) >> 10;
    int b = t * chunk, e = min(b + chunk, NWIN);
    int sum = 0;
    for (int i = b; i < e; i++) sum += c[i];
    s[t] = sum;
    __syncthreads();
    for (int d = 1; d < 1024; d <<= 1) {
        int v = (t >= d) ? s[t - d] : 0;
        __syncthreads();
        s[t] += v;
        __syncthreads();
    }
    int run = (t == 0) ? 0 : s[t - 1];
    for (int i = b; i < e; i++) {
        of[i] = run; cu[i] = run; run += c[i];
    }
    if (t == 0) of[NWIN] = s[1023];
}

__global__ void fill_all(const __grid_constant__ EdgePtrs ep, int* __restrict__ cur,
                         int* __restrict__ csrc)
{
    int r = blockIdx.y;
    int e = blockIdx.x * blockDim.x + threadIdx.x;
    if (e < EDG) {
        int p = atomicAdd(&cur[r * NWIN + ep.ed[r][e]], 1);
        csrc[(size_t)r * EDG + p] = ep.es[r][e];
    }
}

// ================= fused 3-relation gather-mean (256 thr / 4 rows, 8-wide) =========
struct GatherBatch {
    const __half *src[3];
    const int *off[3], *csrc[3];
    int ndst[3];
    __half *o[3];
};

__device__ __forceinline__ void acc8h(float* acc, uint4 q)
{
    const __half2* h2 = (const __half2*)&q;
#pragma unroll
    for (int j = 0; j < 4; j++) {
        float2 f = __half22float2(h2[j]);
        acc[j * 2 + 0] += f.x;
        acc[j * 2 + 1] += f.y;
    }
}

__global__ void gather_all(const __grid_constant__ GatherBatch gb)
{
    int r = blockIdx.y;
    int t = threadIdx.x;
    int d = blockIdx.x * 4 + (t >> 6);
    int c = (t & 63) * 8;
    const __half* src = gb.src[r];

    float acc[8];
#pragma unroll
    for (int j = 0; j < 8; j++) acc[j] = 0.f;
    int deg = 0;
    if (d < gb.ndst[r]) {
        const int* off = gb.off[r];
        const int* cs = gb.csrc[r];
        int s0 = off[d], s1 = off[d + 1];
        deg = s1 - s0;
        int e = s0;
        for (; e + 8 <= s1; e += 8) {
            uint4 q0 = *(const uint4*)(src + (size_t)cs[e + 0] * HDIM + c);
            uint4 q1 = *(const uint4*)(src + (size_t)cs[e + 1] * HDIM + c);
            uint4 q2 = *(const uint4*)(src + (size_t)cs[e + 2] * HDIM + c);
            uint4 q3 = *(const uint4*)(src + (size_t)cs[e + 3] * HDIM + c);
            uint4 q4 = *(const uint4*)(src + (size_t)cs[e + 4] * HDIM + c);
            uint4 q5 = *(const uint4*)(src + (size_t)cs[e + 5] * HDIM + c);
            uint4 q6 = *(const uint4*)(src + (size_t)cs[e + 6] * HDIM + c);
            uint4 q7 = *(const uint4*)(src + (size_t)cs[e + 7] * HDIM + c);
            acc8h(acc, q0); acc8h(acc, q1); acc8h(acc, q2); acc8h(acc, q3);
            acc8h(acc, q4); acc8h(acc, q5); acc8h(acc, q6); acc8h(acc, q7);
        }
        for (; e + 2 <= s1; e += 2) {
            uint4 q0 = *(const uint4*)(src + (size_t)cs[e + 0] * HDIM + c);
            uint4 q1 = *(const uint4*)(src + (size_t)cs[e + 1] * HDIM + c);
            acc8h(acc, q0); acc8h(acc, q1);
        }
        for (; e < s1; e++) {
            uint4 q = *(const uint4*)(src + (size_t)cs[e] * HDIM + c);
            acc8h(acc, q);
        }
    }
    float inv = 1.f / (float)max(deg, 1);
    __half2 o2[4];
#pragma unroll
    for (int j = 0; j < 4; j++)
        o2[j] = __floats2half2_rn(acc[j * 2] * inv, acc[j * 2 + 1] * inv);
    *(uint4*)(gb.o[r] + (size_t)d * HDIM + c) = *(uint4*)o2;
}

// ================= low-dim CSRA pooling =================
__global__ void pool_small(const float* __restrict__ helin,
                           const float* __restrict__ hwlin,
                           const float* __restrict__ score,
                           const int* __restrict__ off, const int* __restrict__ csrc,
                           float* __restrict__ out)
{
    __shared__ float red[128];
    __shared__ float wts[128];
    __shared__ int   idx[128];
    int d = blockIdx.x;
    int t = threadIdx.x;
    if (d >= NWIN) return;
    int s0 = off[d], s1 = off[d + 1];

    float m = -FLT_MAX;
    for (int e = s0 + t; e < s1; e += 128) m = fmaxf(m, score[csrc[e]]);
    red[t] = m; __syncthreads();
    for (int w = 64; w; w >>= 1) {
        if (t < w) red[t] = fmaxf(red[t], red[t + w]);
        __syncthreads();
    }
    float smax = red[0];
    __syncthreads();
    float z = 0.f;
    for (int e = s0 + t; e < s1; e += 128) z += expf(score[csrc[e]] - smax);
    red[t] = z; __syncthreads();
    for (int w = 64; w; w >>= 1) {
        if (t < w) red[t] += red[t + w];
        __syncthreads();
    }
    float invz = 1.f / fmaxf(red[0], 1e-12f);
    __syncthreads();

    float acc = 0.f;
    for (int base = s0; base < s1; base += 128) {
        int e = base + t;
        if (e < s1) {
            int si = csrc[e];
            idx[t] = si;
            wts[t] = expf(score[si] - smax) * invz;
        }
        __syncthreads();
        int cnt = min(128, s1 - base);
        if (t < NOUT) {
            for (int j = 0; j < cnt; j++)
                acc += wts[j] * helin[(size_t)idx[j] * NOUT + t];
        }
        __syncthreads();
    }
    if (t < NOUT)
        out[(size_t)d * NOUT + t] = hwlin[(size_t)d * NOUT + t] + 0.5f * acc;
}

__global__ void gemv_score(const __half* __restrict__ he,
                           const float* __restrict__ w, float* __restrict__ sc)
{
    int row = blockIdx.x * 8 + (threadIdx.x >> 5);
    if (row >= NEX) return;
    int lane = threadIdx.x & 31;
    float s = 0.f;
#pragma unroll
    for (int k = lane * 4; k < HDIM; k += 128) {
        __half2 a = *(const __half2*)(he + (size_t)row * HDIM + k);
        __half2 b = *(const __half2*)(he + (size_t)row * HDIM + k + 2);
        float2 fa = __half22float2(a), fb = __half22float2(b);
        s += fa.x * w[k] + fa.y * w[k + 1] + fb.x * w[k + 2] + fb.y * w[k + 3];
    }
#pragma unroll
    for (int o = 16; o; o >>= 1) s += __shfl_down_sync(0xFFFFFFFFu, s, o);
    if (lane == 0) sc[row] = s;
}

// ================= GEMM common (fp16 single-pass) =================
struct GemmArgs {
    const __half *A[3], *B[3];
    int Kp[3];
    int nops, totChunks;
    int M, Nstore, ldd;
    const float* bias;
    float ps;
    int act;
    float* D;
    __half* Dh;
};
struct GemmPair { GemmArgs g[2]; };

__device__ __forceinline__ uint32_t smem_u32(const void* p) {
    uint32_t a;
    asm("{ .reg .u64 t; cvta.to.shared.u64 t, %1; cvt.u32.u64 %0, t; }" : "=r"(a) : "l"(p));
    return a;
}
__device__ __forceinline__ void cp16(uint32_t dst, const void* src) {
    asm volatile("cp.async.cg.shared.global [%0], [%1], 16;" :: "r"(dst), "l"(src));
}
__device__ __forceinline__ void cp_commit() { asm volatile("cp.async.commit_group;"); }
__device__ __forceinline__ void cp_wait0() { asm volatile("cp.async.wait_group 0;"); }
__device__ __forceinline__ void cp_wait1() { asm volatile("cp.async.wait_group 1;"); }

__device__ __forceinline__ void ldm_x4(uint32_t* r, uint32_t addr) {
    asm volatile("ldmatrix.sync.aligned.m8n8.x4.shared.b16 {%0,%1,%2,%3}, [%4];"
                 : "=r"(r[0]), "=r"(r[1]), "=r"(r[2]), "=r"(r[3]) : "r"(addr));
}
__device__ __forceinline__ void mma16816(float* c, const uint32_t* a, const uint32_t* b) {
    asm volatile("mma.sync.aligned.m16n8k16.row.col.f32.f16.f16.f32 "
                 "{%0,%1,%2,%3},{%4,%5,%6,%7},{%8,%9},{%0,%1,%2,%3};"
                 : "+f"(c[0]), "+f"(c[1]), "+f"(c[2]), "+f"(c[3])
                 : "r"(a[0]), "r"(a[1]), "r"(a[2]), "r"(a[3]), "r"(b[0]), "r"(b[1]));
}

__device__ __forceinline__ void map_oc(const GemmArgs& g, int t, int& o, int& c) {
    o = 0;
    int rem = t;
    while (o < g.nops - 1 && rem >= (g.Kp[o] >> 6)) { rem -= (g.Kp[o] >> 6); o++; }
    c = rem;
}

__device__ __forceinline__ void epi_frag(const GemmArgs& g, const float* a4,
                                         int row0, int col)
{
    if (col >= g.Nstore) return;
    float b0 = 0.f, b1 = 0.f;
    if (g.bias) {
        b0 = g.bias[col];
        if (col + 1 < g.Nstore) b1 = g.bias[col + 1];
    }
#pragma unroll
    for (int rr = 0; rr < 2; rr++) {
        int r = row0 + rr * 8;
        if (r >= g.M) continue;
        float v0 = (a4[rr * 2 + 0] + b0) * g.ps;
        float v1 = (a4[rr * 2 + 1] + b1) * g.ps;
        if (g.act) {
            v0 = v0 > 0.f ? v0 : 0.2f * v0;
            v1 = v1 > 0.f ? v1 : 0.2f * v1;
        }
        if (g.D) {
            float* dp = g.D + (size_t)r * g.ldd + col;
            if (col + 1 < g.Nstore) *(float2*)dp = make_float2(v0, v1);
            else *dp = v0;
        }
        if (g.Dh) {
            *(__half2*)(g.Dh + (size_t)r * HDIM + col) = __floats2half2_rn(v0, v1);
        }
    }
}

// ================= 512-thread 128x256 GEMM (BK=64, R11 config) =================
#define STAGE2      49152      // A 16K, B 32K
#define GEMM_SMEM2  (2 * STAGE2)

__device__ __forceinline__ void load_stage512(const GemmArgs& g, int t, uint32_t sb,
                                              int tid, int m0, int n0)
{
    int o, c;
    map_oc(g, t, o, c);
    const int Kp = g.Kp[o];
    const int k0 = c << 6;
    {
        const __half* a_ = g.A[o] + (size_t)m0 * Kp + k0;
#pragma unroll
        for (int it = 0; it < 2; it++) {
            int idx = it * 512 + tid;
            int r = idx >> 3;
            int j = idx & 7;
            uint32_t sw = r * 128 + ((j ^ (r & 7)) << 4);
            cp16(sb + sw, a_ + (size_t)r * Kp + j * 8);
        }
    }
    {
        const __half* b_ = g.B[o] + (size_t)n0 * Kp + k0;
#pragma unroll
        for (int it = 0; it < 4; it++) {
            int idx = it * 512 + tid;
            int r = idx >> 3;
            int j = idx & 7;
            uint32_t sw = r * 128 + ((j ^ (r & 7)) << 4);
            cp16(sb + 16384 + sw, b_ + (size_t)r * Kp + j * 8);
        }
    }
    cp_commit();
}

__device__ __forceinline__ void gemm_body512(const GemmArgs& g, char* smem)
{
    const uint32_t sbase = smem_u32(smem);
    const int tid = threadIdx.x;
    const int lane = tid & 31;
    const int warp = tid >> 5;
    const int wm = warp >> 2;
    const int wn = warp & 3;
    const int m0 = blockIdx.y * 128;
    const int n0 = blockIdx.x * 256;

    float acc[2][8][4];
#pragma unroll
    for (int i = 0; i < 2; i++)
#pragma unroll
        for (int j = 0; j < 8; j++)
#pragma unroll
            for (int q = 0; q < 4; q++) acc[i][j][q] = 0.f;

    const int sx = lane & 7;
    const int arow = (lane & 7) + ((lane >> 3) & 1) * 8;
    const int khia = (lane >> 4) & 1;
    const int brow = (lane & 7) + ((lane >> 4) & 1) * 8;
    const int khib = (lane >> 3) & 1;

    const int T = g.totChunks;
    load_stage512(g, 0, sbase, tid, m0, n0);

    for (int t = 0; t < T; t++) {
        if (t + 1 < T) {
            load_stage512(g, t + 1, sbase + ((t + 1) & 1) * STAGE2, tid, m0, n0);
            cp_wait1();
        } else {
            cp_wait0();
        }
        __syncthreads();

        const uint32_t Ab = sbase + (t & 1) * STAGE2;
        const uint32_t Bb = Ab + 16384;

#pragma unroll
        for (int ks = 0; ks < 4; ks++) {
            const uint32_t colA = (uint32_t)(((ks * 2 + khia) ^ sx) << 4);
            const uint32_t colB = (uint32_t)(((ks * 2 + khib) ^ sx) << 4);
            uint32_t ah[2][4];
#pragma unroll
            for (int mt = 0; mt < 2; mt++) {
                int row = wm * 32 + mt * 16 + arow;
                ldm_x4(ah[mt], Ab + row * 128 + colA);
            }
#pragma unroll
            for (int half = 0; half < 2; half++) {
                uint32_t bh[2][4];
#pragma unroll
                for (int np = 0; np < 2; np++) {
                    int row = wn * 64 + half * 32 + np * 16 + brow;
                    ldm_x4(bh[np], Bb + row * 128 + colB);
                }
#pragma unroll
                for (int mt = 0; mt < 2; mt++) {
#pragma unroll
                    for (int nt = 0; nt < 4; nt++) {
                        const uint32_t* bf = &bh[nt >> 1][(nt & 1) * 2];
                        mma16816(acc[mt][half * 4 + nt], ah[mt], bf);
                    }
                }
            }
        }
        __syncthreads();
    }

#pragma unroll
    for (int mt = 0; mt < 2; mt++) {
        int row0 = m0 + wm * 32 + mt * 16 + (lane >> 2);
#pragma unroll
        for (int nt = 0; nt < 8; nt++) {
            int col = n0 + wn * 64 + nt * 8 + (lane & 3) * 2;
            epi_frag(g, acc[mt][nt], row0, col);
        }
    }
}

__global__ __launch_bounds__(512, 1) void gemm512_pair(const __grid_constant__ GemmPair p)
{
    extern __shared__ __align__(128) char smem[];
    gemm_body512(p.g[blockIdx.z], smem);
}

// ================= 256-thread 128x128 GEMM =================
#define STAGE_BYTES 32768
#define GEMM_SMEM   (2 * STAGE_BYTES)

__device__ __forceinline__ void load_stage(const GemmArgs& g, int t, uint32_t sb,
                                           int tid, int m0, int n0)
{
    int o, c;
    map_oc(g, t, o, c);
    const int Kp = g.Kp[o];
    const int k0 = c << 6;
    {
        const __half* a_ = g.A[o] + (size_t)m0 * Kp + k0;
#pragma unroll
        for (int it = 0; it < 4; it++) {
            int idx = it * 256 + tid;
            int r = idx >> 3;
            int j = idx & 7;
            uint32_t sw = r * 128 + ((j ^ (r & 7)) << 4);
            cp16(sb + sw, a_ + (size_t)r * Kp + j * 8);
        }
    }
    {
        const __half* b_ = g.B[o] + (size_t)n0 * Kp + k0;
#pragma unroll
        for (int it = 0; it < 4; it++) {
            int idx = it * 256 + tid;
            int r = idx >> 3;
            int j = idx & 7;
            uint32_t sw = r * 128 + ((j ^ (r & 7)) << 4);
            cp16(sb + 16384 + sw, b_ + (size_t)r * Kp + j * 8);
        }
    }
    cp_commit();
}

__device__ __forceinline__ void gemm_body128(const GemmArgs& g, char* smem)
{
    const uint32_t sbase = smem_u32(smem);
    const int tid = threadIdx.x;
    const int lane = tid & 31;
    const int warp = tid >> 5;
    const int wm = warp >> 2;
    const int wn = warp & 3;
    const int m0 = blockIdx.y * 128;
    const int n0 = blockIdx.x * 128;

    float acc[4][4][4];
#pragma unroll
    for (int i = 0; i < 4; i++)
#pragma unroll
        for (int j = 0; j < 4; j++)
#pragma unroll
            for (int q = 0; q < 4; q++) acc[i][j][q] = 0.f;

    const int sx = lane & 7;
    const int arow = (lane & 7) + ((lane >> 3) & 1) * 8;
    const int khia = (lane >> 4) & 1;
    const int brow = (lane & 7) + ((lane >> 4) & 1) * 8;
    const int khib = (lane >> 3) & 1;

    const int T = g.totChunks;
    load_stage(g, 0, sbase, tid, m0, n0);

    for (int t = 0; t < T; t++) {
        if (t + 1 < T) {
            load_stage(g, t + 1, sbase + ((t + 1) & 1) * STAGE_BYTES, tid, m0, n0);
            cp_wait1();
        } else {
            cp_wait0();
        }
        __syncthreads();

        const uint32_t Ab = sbase + (t & 1) * STAGE_BYTES;
        const uint32_t Bb = Ab + 16384;

#pragma unroll
        for (int ks = 0; ks < 4; ks++) {
            uint32_t ah[4][4], bh[2][4];
            const uint32_t colA = (uint32_t)(((ks * 2 + khia) ^ sx) << 4);
            const uint32_t colB = (uint32_t)(((ks * 2 + khib) ^ sx) << 4);
#pragma unroll
            for (int mt = 0; mt < 4; mt++) {
                int row = wm * 64 + mt * 16 + arow;
                ldm_x4(ah[mt], Ab + row * 128 + colA);
            }
#pragma unroll
            for (int np = 0; np < 2; np++) {
                int row = wn * 32 + np * 16 + brow;
                ldm_x4(bh[np], Bb + row * 128 + colB);
            }
#pragma unroll
            for (int mt = 0; mt < 4; mt++) {
#pragma unroll
                for (int nt = 0; nt < 4; nt++) {
                    const uint32_t* bf = &bh[nt >> 1][(nt & 1) * 2];
                    mma16816(acc[mt][nt], ah[mt], bf);
                }
            }
        }
        __syncthreads();
    }

#pragma unroll
    for (int mt = 0; mt < 4; mt++) {
        int row0 = m0 + wm * 64 + mt * 16 + (lane >> 2);
#pragma unroll
        for (int nt = 0; nt < 4; nt++) {
            int col = n0 + wn * 32 + nt * 8 + (lane & 3) * 2;
            epi_frag(g, acc[mt][nt], row0, col);
        }
    }
}

__global__ __launch_bounds__(256, 1) void gemm_mma_pair(const __grid_constant__ GemmPair p)
{
    extern __shared__ __align__(128) char smem[];
    gemm_body128(p.g[blockIdx.z], smem);
}

// ================= host orchestration =================
struct OpDesc {
    const __half *A, *B;
    int Kp;
};

static void fill_args(GemmArgs& g, const OpDesc* ops, int nops, int M, int Nstore,
                      int ldd, const float* bias, float ps, int act,
                      float* D, __half* Dh)
{
    int T = 0;
    for (int o = 0; o < nops; o++) {
        g.A[o] = ops[o].A; g.B[o] = ops[o].B;
        g.Kp[o] = ops[o].Kp;
        T += ops[o].Kp / 64;
    }
    g.nops = nops; g.totChunks = T;
    g.M = M; g.Nstore = Nstore; g.ldd = ldd;
    g.bias = bias; g.ps = ps; g.act = act;
    g.D = D; g.Dh = Dh;
}

extern "C" void kernel_launch(void* const* d_in, const int* in_sizes, int n_in,
                              void* d_out, int out_size)
{
    const float* x_window  = (const float*)d_in[0];
    const float* x_example = (const float*)d_in[1];
    const int*   e_near    = (const int*)d_in[2];
    const int*   e_close   = (const int*)d_in[3];
    const int*   e_refer   = (const int*)d_in[4];
    const float* W_win     = (const float*)d_in[5];
    const float* W_exp     = (const float*)d_in[6];
    const float* W_post    = (const float*)d_in[7];
    const float* Wl_near   = (const float*)d_in[9];
    const float* Wr_near   = (const float*)d_in[10];
    const float* b_near    = (const float*)d_in[11];
    const float* Wl_close  = (const float*)d_in[12];
    const float* Wr_close  = (const float*)d_in[13];
    const float* b_close   = (const float*)d_in[14];
    const float* Wl_refer  = (const float*)d_in[15];
    const float* Wr_refer  = (const float*)d_in[16];
    const float* b_refer   = (const float*)d_in[17];
    const float* w_pool    = (const float*)d_in[18];
    const float* W_lin     = (const float*)d_in[19];
    const float* b_lin     = (const float*)d_in[20];
    float* out = (float*)d_out;

    cudaFuncSetAttribute(gemm_mma_pair, cudaFuncAttributeMaxDynamicSharedMemorySize, GEMM_SMEM);
    cudaFuncSetAttribute(gemm512_pair, cudaFuncAttributeMaxDynamicSharedMemorySize, GEMM_SMEM2);

    float *score, *bsum, *lin0, *lin1;
    int *cnt, *off, *cur, *csrc;
    __half *wt, *big, *pt;
    __half *phw[2], *phe[2], *pa0, *pa1, *pa2;
    cudaGetSymbolAddress((void**)&score, g_score);
    cudaGetSymbolAddress((void**)&bsum, g_bsum);
    cudaGetSymbolAddress((void**)&lin0, g_lin0);
    cudaGetSymbolAddress((void**)&lin1, g_lin1);
    cudaGetSymbolAddress((void**)&cnt, g_cnt);
    cudaGetSymbolAddress((void**)&off, g_off);
    cudaGetSymbolAddress((void**)&cur, g_cur);
    cudaGetSymbolAddress((void**)&csrc, g_csrc);
    cudaGetSymbolAddress((void**)&wt, g_wt);
    cudaGetSymbolAddress((void**)&big, g_big);
    cudaGetSymbolAddress((void**)&pt, g_pt);
    cudaGetSymbolAddress((void**)&phw[0], g_phw0);
    cudaGetSymbolAddress((void**)&phw[1], g_phw1);
    cudaGetSymbolAddress((void**)&phe[0], g_phe0);
    cudaGetSymbolAddress((void**)&phe[1], g_phe1);
    cudaGetSymbolAddress((void**)&pa0, g_pa0);
    cudaGetSymbolAddress((void**)&pa1, g_pa1);
    cudaGetSymbolAddress((void**)&pa2, g_pa2);

    const unsigned edge_blocks = (EDG + 255) / 256;

    // --- batched weight conversion ---
    {
        ConvBatch cb;
        for (int l = 0; l < NLAYERS; l++) {
            size_t s = (size_t)l * HDIM * HDIM;
            cb.W1[l * 5 + 0] = Wl_near + s;  cb.W2[l * 5 + 0] = nullptr;      cb.dstoff[l * 5 + 0] = WOFF_WLN(l);
            cb.W1[l * 5 + 1] = Wl_refer + s; cb.W2[l * 5 + 1] = nullptr;      cb.dstoff[l * 5 + 1] = WOFF_WLR(l);
            cb.W1[l * 5 + 2] = Wr_near + s;  cb.W2[l * 5 + 2] = Wr_refer + s; cb.dstoff[l * 5 + 2] = WOFF_WSUM(l);
            cb.W1[l * 5 + 3] = Wl_close + s; cb.W2[l * 5 + 3] = nullptr;      cb.dstoff[l * 5 + 3] = WOFF_WLC(l);
            cb.W1[l * 5 + 4] = Wr_close + s; cb.W2[l * 5 + 4] = nullptr;      cb.dstoff[l * 5 + 4] = WOFF_WRC(l);
        }
        cb.W1[20] = W_post; cb.W2[20] = nullptr; cb.dstoff[20] = WOFF_POST;
        dim3 blk(32, 8);
        dim3 gB(HDIM / 32, HDIM / 32, NBATCH);
        conv_w_batch<<<gB, blk>>>(cb, wt);

        dim3 gWIN(KP_WIN / 32, HDIM / 32);
        conv_w<<<gWIN, blk>>>(W_win, KWIN, HDIM, KP_WIN, wt + WOFF_WIN);
        dim3 gEXP(128 / 32, HDIM / 32);
        conv_w<<<gEXP, blk>>>(W_exp, KEXP, HDIM, 128, wt + WOFF_EXP);
        dim3 gLIN(HDIM / 32, 128 / 32);
        conv_w<<<gLIN, blk>>>(W_lin, HDIM, NOUT, HDIM, wt + WOFF_LIN);
        bias_sum_all<<<(NLAYERS * HDIM + 255) / 256, 256>>>(b_near, b_refer, bsum);
    }

    // --- CSR build ---
    {
        EdgePtrs ep;
        ep.es[0] = e_near;  ep.ed[0] = e_near + EDG;
        ep.es[1] = e_refer; ep.ed[1] = e_refer + EDG;
        ep.es[2] = e_close; ep.ed[2] = e_close + EDG;
        zero_int<<<(3 * NWIN + 255) / 256, 256>>>(cnt, 3 * NWIN);
        dim3 ge(edge_blocks, 3);
        hist_all<<<ge, 256>>>(ep, cnt);
        scan_all<<<3, 1024>>>(cnt, off, cur);
        fill_all<<<ge, 256>>>(ep, cur, csrc);
    }

    // --- input projections (paired, 512-thread GEMM) ---
    {
        long long tot = (long long)MP * 128;
        conv_a<<<(unsigned)((tot + 255) / 256), 256>>>(x_example, NEX, KEXP, 128, tot, pa0);
        tot = (long long)MP * KP_WIN;
        conv_a<<<(unsigned)((tot + 255) / 256), 256>>>(x_window, NWIN, KWIN, KP_WIN, tot, big);

        GemmPair pr;
        OpDesc opw = { big, wt + WOFF_WIN, KP_WIN };
        OpDesc ope = { pa0, wt + WOFF_EXP, 128 };
        fill_args(pr.g[0], &opw, 1, NWIN, HDIM, HDIM, nullptr, 1.f, 1, nullptr, pt);
        fill_args(pr.g[1], &ope, 1, NEX, HDIM, HDIM, nullptr, 1.f, 1, nullptr, pa1);
        gemm512_pair<<<dim3(2, 235, 2), 512, GEMM_SMEM2>>>(pr);

        OpDesc opw2 = { pt, wt + WOFF_POST, HDIM };
        OpDesc ope2 = { pa1, wt + WOFF_POST, HDIM };
        fill_args(pr.g[0], &opw2, 1, NWIN, HDIM, HDIM, nullptr, 1.f, 1, nullptr, phw[0]);
        fill_args(pr.g[1], &ope2, 1, NEX, HDIM, HDIM, nullptr, 1.f, 1, nullptr, phe[0]);
        gemm512_pair<<<dim3(2, 235, 2), 512, GEMM_SMEM2>>>(pr);
    }

    // --- SAGE layers ---
    int curb = 0;
    for (int l = 0; l < NLAYERS; l++) {
        int nxt = curb ^ 1;
        GatherBatch gb;
        gb.src[0] = phw[curb];
        gb.src[1] = phe[curb];
        gb.src[2] = phe[curb];
        gb.off[0] = off + 0 * (NWIN + 1); gb.csrc[0] = csrc + 0 * (size_t)EDG; gb.ndst[0] = NWIN;
        gb.off[1] = off + 1 * (NWIN + 1); gb.csrc[1] = csrc + 1 * (size_t)EDG; gb.ndst[1] = NWIN;
        gb.off[2] = off + 2 * (NWIN + 1); gb.csrc[2] = csrc + 2 * (size_t)EDG; gb.ndst[2] = NEX;
        gb.o[0] = pa0; gb.o[1] = pa1; gb.o[2] = pa2;
        gather_all<<<dim3(MP / 4, 3), 256>>>(gb);

        GemmPair pr;
        OpDesc ops3[3] = {
            { pa0, wt + WOFF_WLN(l), HDIM },
            { pa1, wt + WOFF_WLR(l), HDIM },
            { phw[curb], wt + WOFF_WSUM(l), HDIM },
        };
        OpDesc ops2[2] = {
            { pa2, wt + WOFF_WLC(l), HDIM },
            { phe[curb], wt + WOFF_WRC(l), HDIM },
        };
        fill_args(pr.g[0], ops3, 3, NWIN, HDIM, HDIM, bsum + (size_t)l * HDIM, 0.5f, 1,
                  nullptr, phw[nxt]);
        fill_args(pr.g[1], ops2, 2, NEX, HDIM, HDIM, b_close + (size_t)l * HDIM, 1.f, 1,
                  nullptr, phe[nxt]);
        gemm512_pair<<<dim3(2, 235, 2), 512, GEMM_SMEM2>>>(pr);
        curb = nxt;
    }

    // --- score + low-dim projections (paired 128-wide GEMM) ---
    gemv_score<<<(NEX + 7) / 8, 256>>>(phe[curb], w_pool, score);
    {
        GemmPair pr;
        OpDesc opw = { phw[curb], wt + WOFF_LIN, HDIM };
        OpDesc ope = { phe[curb], wt + WOFF_LIN, HDIM };
        fill_args(pr.g[0], &opw, 1, NWIN, NOUT, NOUT, b_lin, 1.f, 0, lin0, nullptr);
        fill_args(pr.g[1], &ope, 1, NEX, NOUT, NOUT, nullptr, 1.f, 0, lin1, nullptr);
        gemm_mma_pair<<<dim3(1, 235, 2), 256, GEMM_SMEM>>>(pr);
    }

    // --- low-dim CSRA pooling -> out directly ---
    pool_small<<<NWIN, 128>>>(lin1, lin0, score,
                              off + 1 * (NWIN + 1), csrc + 1 * (size_t)EDG, out);
}

// round 14
// speedup vs baseline: 1.0077x; 1.0077x over previous
#include <cuda_runtime.h>
#include <cuda_fp16.h>
#include <float.h>
#include <math.h>
#include <stdint.h>

#define NWIN 30000
#define NEX  30000
#define EDG  480000
#define HDIM 512
#define NLAYERS 4
#define KWIN 1949
#define KEXP 100
#define NOUT 100
#define MP   30080
#define KP_WIN 1984

// ================= small fp32 scratch =================
__device__ float g_score[NEX];
__device__ float g_bsum[NLAYERS*HDIM];
__device__ __align__(256) float g_lin0[NWIN*NOUT];
__device__ __align__(256) float g_lin1[NEX*NOUT];

// ================= CSR scratch =================
__device__ int g_cnt[3*NWIN];
__device__ int g_off[3*(NWIN+1)];
__device__ int g_cur[3*NWIN];
__device__ int g_csrc[3*EDG];

// ================= fp16 weight buffers [N][Kp] =================
#define WOFF_STEP   (HDIM*HDIM)
#define WOFF_LAYER  (5*WOFF_STEP)
#define WOFF_WLN(l) ((l)*WOFF_LAYER + 0*WOFF_STEP)
#define WOFF_WLR(l) ((l)*WOFF_LAYER + 1*WOFF_STEP)
#define WOFF_WSUM(l)((l)*WOFF_LAYER + 2*WOFF_STEP)
#define WOFF_WLC(l) ((l)*WOFF_LAYER + 3*WOFF_STEP)
#define WOFF_WRC(l) ((l)*WOFF_LAYER + 4*WOFF_STEP)
#define WOFF_POST   (NLAYERS*WOFF_LAYER)
#define WOFF_WIN    (WOFF_POST + WOFF_STEP)
#define WOFF_EXP    (WOFF_WIN + HDIM*KP_WIN)
#define WOFF_LIN    (WOFF_EXP + HDIM*128)
#define WTOTAL      (WOFF_LIN + 128*HDIM)
__device__ __align__(256) __half g_wt[WTOTAL];

// ================= fp16 activation plane buffers =================
__device__ __align__(256) __half g_big[(size_t)MP*KP_WIN];
__device__ __align__(256) __half g_pt[(size_t)MP*HDIM];
__device__ __align__(256) __half g_phw0[(size_t)MP*HDIM];
__device__ __align__(256) __half g_phw1[(size_t)MP*HDIM];
__device__ __align__(256) __half g_phe0[(size_t)MP*HDIM];
__device__ __align__(256) __half g_phe1[(size_t)MP*HDIM];
__device__ __align__(256) __half g_pa0[(size_t)MP*HDIM];
__device__ __align__(256) __half g_pa1[(size_t)MP*HDIM];
__device__ __align__(256) __half g_pa2[(size_t)MP*HDIM];

// ================= batched HxH weight conversion =================
#define NBATCH 21
struct ConvBatch {
    const float* W1[NBATCH];
    const float* W2[NBATCH];
    int dstoff[NBATCH];
};

__global__ void conv_w_batch(const __grid_constant__ ConvBatch cb,
                             __half* __restrict__ ob)
{
    __shared__ float t[32][33];
    int z = blockIdx.z;
    const float* W = cb.W1[z];
    const float* W2 = cb.W2[z];
    __half* o = ob + cb.dstoff[z];
    int k0 = blockIdx.x * 32, n0 = blockIdx.y * 32;
    int tx = threadIdx.x, ty = threadIdx.y;
#pragma unroll
    for (int i = 0; i < 4; i++) {
        int k = k0 + ty + i * 8, n = n0 + tx;
        float v = W[(size_t)k * HDIM + n];
        if (W2) v += W2[(size_t)k * HDIM + n];
        t[ty + i * 8][tx] = v;
    }
    __syncthreads();
#pragma unroll
    for (int i = 0; i < 4; i++) {
        int n = n0 + ty + i * 8, k = k0 + tx;
        o[(size_t)n * HDIM + k] = __float2half_rn(t[tx][ty + i * 8]);
    }
}

__global__ void conv_w(const float* __restrict__ W, int K, int N, int Kp,
                       __half* __restrict__ o)
{
    __shared__ float t[32][33];
    int k0 = blockIdx.x * 32, n0 = blockIdx.y * 32;
    int tx = threadIdx.x, ty = threadIdx.y;
#pragma unroll
    for (int i = 0; i < 4; i++) {
        int k = k0 + ty + i * 8, n = n0 + tx;
        float v = 0.f;
        if (k < K && n < N) v = W[(size_t)k * N + n];
        t[ty + i * 8][tx] = v;
    }
    __syncthreads();
#pragma unroll
    for (int i = 0; i < 4; i++) {
        int n = n0 + ty + i * 8, k = k0 + tx;
        o[(size_t)n * Kp + k] = __float2half_rn(t[tx][ty + i * 8]);
    }
}

__global__ void conv_a(const float* __restrict__ A, int M, int K, int Kp, long long total,
                       __half* __restrict__ o)
{
    long long i = (long long)blockIdx.x * blockDim.x + threadIdx.x;
    if (i >= total) return;
    int m = (int)(i / Kp);
    int k = (int)(i % Kp);
    float v = 0.f;
    if (m < M && k < K) v = A[(size_t)m * K + k];
    o[i] = __float2half_rn(v);
}

__global__ void bias_sum_all(const float* a, const float* b, float* o)
{
    int i = blockIdx.x * blockDim.x + threadIdx.x;
    if (i < NLAYERS * HDIM) o[i] = a[i] + b[i];
}

__global__ void zero_int(int* p, int n)
{
    int i = blockIdx.x * blockDim.x + threadIdx.x;
    if (i < n) p[i] = 0;
}

// ================= CSR build =================
struct EdgePtrs { const int* es[3]; const int* ed[3]; };

__global__ void hist_all(const __grid_constant__ EdgePtrs ep, int* __restrict__ cnt)
{
    int r = blockIdx.y;
    int e = blockIdx.x * blockDim.x + threadIdx.x;
    if (e < EDG) atomicAdd(&cnt[r * NWIN + ep.ed[r][e]], 1);
}

__global__ void scan_all(const int* __restrict__ cnt, int* __restrict__ off,
                         int* __restrict__ cur)
{
    __shared__ int s[1024];
    int r = blockIdx.x;
    const int* c = cnt + r * NWIN;
    int* of = off + r * (NWIN + 1);
    int* cu = cur + r * NWIN;
    int t = threadIdx.x;
    int chunk = (NWIN + 1023) >> 10;
    int b = t * chunk, e = min(b + chunk, NWIN);
    int sum = 0;
    for (int i = b; i < e; i++) sum += c[i];
    s[t] = sum;
    __syncthreads();
    for (int d = 1; d < 1024; d <<= 1) {
        int v = (t >= d) ? s[t - d] : 0;
        __syncthreads();
        s[t] += v;
        __syncthreads();
    }
    int run = (t == 0) ? 0 : s[t - 1];
    for (int i = b; i < e; i++) {
        of[i] = run; cu[i] = run; run += c[i];
    }
    if (t == 0) of[NWIN] = s[1023];
}

__global__ void fill_all(const __grid_constant__ EdgePtrs ep, int* __restrict__ cur,
                         int* __restrict__ csrc)
{
    int r = blockIdx.y;
    int e = blockIdx.x * blockDim.x + threadIdx.x;
    if (e < EDG) {
        int p = atomicAdd(&cur[r * NWIN + ep.ed[r][e]], 1);
        csrc[(size_t)r * EDG + p] = ep.es[r][e];
    }
}

// ================= fused 3-relation gather-mean (128 thr / 2 rows, 8-wide MLP) =====
struct GatherBatch {
    const __half *src[3];
    const int *off[3], *csrc[3];
    int ndst[3];
    __half *o[3];
};

__device__ __forceinline__ void acc8h(float* acc, uint4 q)
{
    const __half2* h2 = (const __half2*)&q;
#pragma unroll
    for (int j = 0; j < 4; j++) {
        float2 f = __half22float2(h2[j]);
        acc[j * 2 + 0] += f.x;
        acc[j * 2 + 1] += f.y;
    }
}

__global__ void gather_all(const __grid_constant__ GatherBatch gb)
{
    int r = blockIdx.y;
    int t = threadIdx.x;
    int d = blockIdx.x * 2 + (t >> 6);
    int c = (t & 63) * 8;
    const __half* src = gb.src[r];

    float acc[8];
#pragma unroll
    for (int j = 0; j < 8; j++) acc[j] = 0.f;
    int deg = 0;
    if (d < gb.ndst[r]) {
        const int* off = gb.off[r];
        const int* cs = gb.csrc[r];
        int s0 = off[d], s1 = off[d + 1];
        deg = s1 - s0;
        int e = s0;
        for (; e + 8 <= s1; e += 8) {
            uint4 q0 = *(const uint4*)(src + (size_t)cs[e + 0] * HDIM + c);
            uint4 q1 = *(const uint4*)(src + (size_t)cs[e + 1] * HDIM + c);
            uint4 q2 = *(const uint4*)(src + (size_t)cs[e + 2] * HDIM + c);
            uint4 q3 = *(const uint4*)(src + (size_t)cs[e + 3] * HDIM + c);
            uint4 q4 = *(const uint4*)(src + (size_t)cs[e + 4] * HDIM + c);
            uint4 q5 = *(const uint4*)(src + (size_t)cs[e + 5] * HDIM + c);
            uint4 q6 = *(const uint4*)(src + (size_t)cs[e + 6] * HDIM + c);
            uint4 q7 = *(const uint4*)(src + (size_t)cs[e + 7] * HDIM + c);
            acc8h(acc, q0); acc8h(acc, q1); acc8h(acc, q2); acc8h(acc, q3);
            acc8h(acc, q4); acc8h(acc, q5); acc8h(acc, q6); acc8h(acc, q7);
        }
        for (; e + 4 <= s1; e += 4) {
            uint4 q0 = *(const uint4*)(src + (size_t)cs[e + 0] * HDIM + c);
            uint4 q1 = *(const uint4*)(src + (size_t)cs[e + 1] * HDIM + c);
            uint4 q2 = *(const uint4*)(src + (size_t)cs[e + 2] * HDIM + c);
            uint4 q3 = *(const uint4*)(src + (size_t)cs[e + 3] * HDIM + c);
            acc8h(acc, q0); acc8h(acc, q1); acc8h(acc, q2); acc8h(acc, q3);
        }
        for (; e < s1; e++) {
            uint4 q = *(const uint4*)(src + (size_t)cs[e] * HDIM + c);
            acc8h(acc, q);
        }
    }
    float inv = 1.f / (float)max(deg, 1);
    __half2 o2[4];
#pragma unroll
    for (int j = 0; j < 4; j++)
        o2[j] = __floats2half2_rn(acc[j * 2] * inv, acc[j * 2 + 1] * inv);
    *(uint4*)(gb.o[r] + (size_t)d * HDIM + c) = *(uint4*)o2;
}

// ================= low-dim CSRA pooling =================
__global__ void pool_small(const float* __restrict__ helin,
                           const float* __restrict__ hwlin,
                           const float* __restrict__ score,
                           const int* __restrict__ off, const int* __restrict__ csrc,
                           float* __restrict__ out)
{
    __shared__ float red[128];
    __shared__ float wts[128];
    __shared__ int   idx[128];
    int d = blockIdx.x;
    int t = threadIdx.x;
    if (d >= NWIN) return;
    int s0 = off[d], s1 = off[d + 1];

    float m = -FLT_MAX;
    for (int e = s0 + t; e < s1; e += 128) m = fmaxf(m, score[csrc[e]]);
    red[t] = m; __syncthreads();
    for (int w = 64; w; w >>= 1) {
        if (t < w) red[t] = fmaxf(red[t], red[t + w]);
        __syncthreads();
    }
    float smax = red[0];
    __syncthreads();
    float z = 0.f;
    for (int e = s0 + t; e < s1; e += 128) z += expf(score[csrc[e]] - smax);
    red[t] = z; __syncthreads();
    for (int w = 64; w; w >>= 1) {
        if (t < w) red[t] += red[t + w];
        __syncthreads();
    }
    float invz = 1.f / fmaxf(red[0], 1e-12f);
    __syncthreads();

    float acc = 0.f;
    for (int base = s0; base < s1; base += 128) {
        int e = base + t;
        if (e < s1) {
            int si = csrc[e];
            idx[t] = si;
            wts[t] = expf(score[si] - smax) * invz;
        }
        __syncthreads();
        int cnt = min(128, s1 - base);
        if (t < NOUT) {
            for (int j = 0; j < cnt; j++)
                acc += wts[j] * helin[(size_t)idx[j] * NOUT + t];
        }
        __syncthreads();
    }
    if (t < NOUT)
        out[(size_t)d * NOUT + t] = hwlin[(size_t)d * NOUT + t] + 0.5f * acc;
}

__global__ void gemv_score(const __half* __restrict__ he,
                           const float* __restrict__ w, float* __restrict__ sc)
{
    int row = blockIdx.x * 8 + (threadIdx.x >> 5);
    if (row >= NEX) return;
    int lane = threadIdx.x & 31;
    float s = 0.f;
#pragma unroll
    for (int k = lane * 4; k < HDIM; k += 128) {
        __half2 a = *(const __half2*)(he + (size_t)row * HDIM + k);
        __half2 b = *(const __half2*)(he + (size_t)row * HDIM + k + 2);
        float2 fa = __half22float2(a), fb = __half22float2(b);
        s += fa.x * w[k] + fa.y * w[k + 1] + fb.x * w[k + 2] + fb.y * w[k + 3];
    }
#pragma unroll
    for (int o = 16; o; o >>= 1) s += __shfl_down_sync(0xFFFFFFFFu, s, o);
    if (lane == 0) sc[row] = s;
}

// ================= GEMM common (fp16 single-pass) =================
struct GemmArgs {
    const __half *A[3], *B[3];
    int Kp[3];
    int nops, totChunks;
    int M, Nstore, ldd;
    const float* bias;
    float ps;
    int act;
    float* D;
    __half* Dh;
};
struct GemmPair { GemmArgs g[2]; };

__device__ __forceinline__ uint32_t smem_u32(const void* p) {
    uint32_t a;
    asm("{ .reg .u64 t; cvta.to.shared.u64 t, %1; cvt.u32.u64 %0, t; }" : "=r"(a) : "l"(p));
    return a;
}
__device__ __forceinline__ void cp16(uint32_t dst, const void* src) {
    asm volatile("cp.async.cg.shared.global [%0], [%1], 16;" :: "r"(dst), "l"(src));
}
__device__ __forceinline__ void cp_commit() { asm volatile("cp.async.commit_group;"); }
__device__ __forceinline__ void cp_wait0() { asm volatile("cp.async.wait_group 0;"); }
__device__ __forceinline__ void cp_wait1() { asm volatile("cp.async.wait_group 1;"); }

__device__ __forceinline__ void ldm_x4(uint32_t* r, uint32_t addr) {
    asm volatile("ldmatrix.sync.aligned.m8n8.x4.shared.b16 {%0,%1,%2,%3}, [%4];"
                 : "=r"(r[0]), "=r"(r[1]), "=r"(r[2]), "=r"(r[3]) : "r"(addr));
}
__device__ __forceinline__ void mma16816(float* c, const uint32_t* a, const uint32_t* b) {
    asm volatile("mma.sync.aligned.m16n8k16.row.col.f32.f16.f16.f32 "
                 "{%0,%1,%2,%3},{%4,%5,%6,%7},{%8,%9},{%0,%1,%2,%3};"
                 : "+f"(c[0]), "+f"(c[1]), "+f"(c[2]), "+f"(c[3])
                 : "r"(a[0]), "r"(a[1]), "r"(a[2]), "r"(a[3]), "r"(b[0]), "r"(b[1]));
}

__device__ __forceinline__ void map_oc(const GemmArgs& g, int t, int& o, int& c) {
    o = 0;
    int rem = t;
    while (o < g.nops - 1 && rem >= (g.Kp[o] >> 6)) { rem -= (g.Kp[o] >> 6); o++; }
    c = rem;
}

__device__ __forceinline__ void epi_frag(const GemmArgs& g, const float* a4,
                                         int row0, int col)
{
    if (col >= g.Nstore) return;
    float b0 = 0.f, b1 = 0.f;
    if (g.bias) {
        b0 = g.bias[col];
        if (col + 1 < g.Nstore) b1 = g.bias[col + 1];
    }
#pragma unroll
    for (int rr = 0; rr < 2; rr++) {
        int r = row0 + rr * 8;
        if (r >= g.M) continue;
        float v0 = (a4[rr * 2 + 0] + b0) * g.ps;
        float v1 = (a4[rr * 2 + 1] + b1) * g.ps;
        if (g.act) {
            v0 = v0 > 0.f ? v0 : 0.2f * v0;
            v1 = v1 > 0.f ? v1 : 0.2f * v1;
        }
        if (g.D) {
            float* dp = g.D + (size_t)r * g.ldd + col;
            if (col + 1 < g.Nstore) *(float2*)dp = make_float2(v0, v1);
            else *dp = v0;
        }
        if (g.Dh) {
            *(__half2*)(g.Dh + (size_t)r * HDIM + col) = __floats2half2_rn(v0, v1);
        }
    }
}

// ================= 512-thread 128x256 GEMM (BK=64) =================
#define STAGE2      49152      // A 16K, B 32K
#define GEMM_SMEM2  (2 * STAGE2)

__device__ __forceinline__ void load_stage512(const GemmArgs& g, int t, uint32_t sb,
                                              int tid, int m0, int n0)
{
    int o, c;
    map_oc(g, t, o, c);
    const int Kp = g.Kp[o];
    const int k0 = c << 6;
    {
        const __half* a_ = g.A[o] + (size_t)m0 * Kp + k0;
#pragma unroll
        for (int it = 0; it < 2; it++) {
            int idx = it * 512 + tid;
            int r = idx >> 3;
            int j = idx & 7;
            uint32_t sw = r * 128 + ((j ^ (r & 7)) << 4);
            cp16(sb + sw, a_ + (size_t)r * Kp + j * 8);
        }
    }
    {
        const __half* b_ = g.B[o] + (size_t)n0 * Kp + k0;
#pragma unroll
        for (int it = 0; it < 4; it++) {
            int idx = it * 512 + tid;
            int r = idx >> 3;
            int j = idx & 7;
            uint32_t sw = r * 128 + ((j ^ (r & 7)) << 4);
            cp16(sb + 16384 + sw, b_ + (size_t)r * Kp + j * 8);
        }
    }
    cp_commit();
}

__device__ __forceinline__ void gemm_body512(const GemmArgs& g, char* smem)
{
    const uint32_t sbase = smem_u32(smem);
    const int tid = threadIdx.x;
    const int lane = tid & 31;
    const int warp = tid >> 5;
    const int wm = warp >> 2;
    const int wn = warp & 3;
    const int m0 = blockIdx.y * 128;
    const int n0 = blockIdx.x * 256;

    float acc[2][8][4];
#pragma unroll
    for (int i = 0; i < 2; i++)
#pragma unroll
        for (int j = 0; j < 8; j++)
#pragma unroll
            for (int q = 0; q < 4; q++) acc[i][j][q] = 0.f;

    const int sx = lane & 7;
    const int arow = (lane & 7) + ((lane >> 3) & 1) * 8;
    const int khia = (lane >> 4) & 1;
    const int brow = (lane & 7) + ((lane >> 4) & 1) * 8;
    const int khib = (lane >> 3) & 1;

    const int T = g.totChunks;
    load_stage512(g, 0, sbase, tid, m0, n0);

    for (int t = 0; t < T; t++) {
        if (t + 1 < T) {
            load_stage512(g, t + 1, sbase + ((t + 1) & 1) * STAGE2, tid, m0, n0);
            cp_wait1();
        } else {
            cp_wait0();
        }
        __syncthreads();

        const uint32_t Ab = sbase + (t & 1) * STAGE2;
        const uint32_t Bb = Ab + 16384;

#pragma unroll
        for (int ks = 0; ks < 4; ks++) {
            const uint32_t colA = (uint32_t)(((ks * 2 + khia) ^ sx) << 4);
            const uint32_t colB = (uint32_t)(((ks * 2 + khib) ^ sx) << 4);
            uint32_t ah[2][4];
#pragma unroll
            for (int mt = 0; mt < 2; mt++) {
                int row = wm * 32 + mt * 16 + arow;
                ldm_x4(ah[mt], Ab + row * 128 + colA);
            }
#pragma unroll
            for (int half = 0; half < 2; half++) {
                uint32_t bh[2][4];
#pragma unroll
                for (int np = 0; np < 2; np++) {
                    int row = wn * 64 + half * 32 + np * 16 + brow;
                    ldm_x4(bh[np], Bb + row * 128 + colB);
                }
#pragma unroll
                for (int mt = 0; mt < 2; mt++) {
#pragma unroll
                    for (int nt = 0; nt < 4; nt++) {
                        const uint32_t* bf = &bh[nt >> 1][(nt & 1) * 2];
                        mma16816(acc[mt][half * 4 + nt], ah[mt], bf);
                    }
                }
            }
        }
        __syncthreads();
    }

#pragma unroll
    for (int mt = 0; mt < 2; mt++) {
        int row0 = m0 + wm * 32 + mt * 16 + (lane >> 2);
#pragma unroll
        for (int nt = 0; nt < 8; nt++) {
            int col = n0 + wn * 64 + nt * 8 + (lane & 3) * 2;
            epi_frag(g, acc[mt][nt], row0, col);
        }
    }
}

__global__ __launch_bounds__(512, 1) void gemm512_pair(const __grid_constant__ GemmPair p)
{
    extern __shared__ __align__(128) char smem[];
    gemm_body512(p.g[blockIdx.z], smem);
}

// ================= 256-thread 128x128 GEMM =================
#define STAGE_BYTES 32768
#define GEMM_SMEM   (2 * STAGE_BYTES)

__device__ __forceinline__ void load_stage(const GemmArgs& g, int t, uint32_t sb,
                                           int tid, int m0, int n0)
{
    int o, c;
    map_oc(g, t, o, c);
    const int Kp = g.Kp[o];
    const int k0 = c << 6;
    {
        const __half* a_ = g.A[o] + (size_t)m0 * Kp + k0;
#pragma unroll
        for (int it = 0; it < 4; it++) {
            int idx = it * 256 + tid;
            int r = idx >> 3;
            int j = idx & 7;
            uint32_t sw = r * 128 + ((j ^ (r & 7)) << 4);
            cp16(sb + sw, a_ + (size_t)r * Kp + j * 8);
        }
    }
    {
        const __half* b_ = g.B[o] + (size_t)n0 * Kp + k0;
#pragma unroll
        for (int it = 0; it < 4; it++) {
            int idx = it * 256 + tid;
            int r = idx >> 3;
            int j = idx & 7;
            uint32_t sw = r * 128 + ((j ^ (r & 7)) << 4);
            cp16(sb + 16384 + sw, b_ + (size_t)r * Kp + j * 8);
        }
    }
    cp_commit();
}

__device__ __forceinline__ void gemm_body128(const GemmArgs& g, char* smem)
{
    const uint32_t sbase = smem_u32(smem);
    const int tid = threadIdx.x;
    const int lane = tid & 31;
    const int warp = tid >> 5;
    const int wm = warp >> 2;
    const int wn = warp & 3;
    const int m0 = blockIdx.y * 128;
    const int n0 = blockIdx.x * 128;

    float acc[4][4][4];
#pragma unroll
    for (int i = 0; i < 4; i++)
#pragma unroll
        for (int j = 0; j < 4; j++)
#pragma unroll
            for (int q = 0; q < 4; q++) acc[i][j][q] = 0.f;

    const int sx = lane & 7;
    const int arow = (lane & 7) + ((lane >> 3) & 1) * 8;
    const int khia = (lane >> 4) & 1;
    const int brow = (lane & 7) + ((lane >> 4) & 1) * 8;
    const int khib = (lane >> 3) & 1;

    const int T = g.totChunks;
    load_stage(g, 0, sbase, tid, m0, n0);

    for (int t = 0; t < T; t++) {
        if (t + 1 < T) {
            load_stage(g, t + 1, sbase + ((t + 1) & 1) * STAGE_BYTES, tid, m0, n0);
            cp_wait1();
        } else {
            cp_wait0();
        }
        __syncthreads();

        const uint32_t Ab = sbase + (t & 1) * STAGE_BYTES;
        const uint32_t Bb = Ab + 16384;

#pragma unroll
        for (int ks = 0; ks < 4; ks++) {
            uint32_t ah[4][4], bh[2][4];
            const uint32_t colA = (uint32_t)(((ks * 2 + khia) ^ sx) << 4);
            const uint32_t colB = (uint32_t)(((ks * 2 + khib) ^ sx) << 4);
#pragma unroll
            for (int mt = 0; mt < 4; mt++) {
                int row = wm * 64 + mt * 16 + arow;
                ldm_x4(ah[mt], Ab + row * 128 + colA);
            }
#pragma unroll
            for (int np = 0; np < 2; np++) {
                int row = wn * 32 + np * 16 + brow;
                ldm_x4(bh[np], Bb + row * 128 + colB);
            }
#pragma unroll
            for (int mt = 0; mt < 4; mt++) {
#pragma unroll
                for (int nt = 0; nt < 4; nt++) {
                    const uint32_t* bf = &bh[nt >> 1][(nt & 1) * 2];
                    mma16816(acc[mt][nt], ah[mt], bf);
                }
            }
        }
        __syncthreads();
    }

#pragma unroll
    for (int mt = 0; mt < 4; mt++) {
        int row0 = m0 + wm * 64 + mt * 16 + (lane >> 2);
#pragma unroll
        for (int nt = 0; nt < 4; nt++) {
            int col = n0 + wn * 32 + nt * 8 + (lane & 3) * 2;
            epi_frag(g, acc[mt][nt], row0, col);
        }
    }
}

__global__ __launch_bounds__(256, 1) void gemm_mma_pair(const __grid_constant__ GemmPair p)
{
    extern __shared__ __align__(128) char smem[];
    gemm_body128(p.g[blockIdx.z], smem);
}

// ================= host orchestration =================
struct OpDesc {
    const __half *A, *B;
    int Kp;
};

static void fill_args(GemmArgs& g, const OpDesc* ops, int nops, int M, int Nstore,
                      int ldd, const float* bias, float ps, int act,
                      float* D, __half* Dh)
{
    int T = 0;
    for (int o = 0; o < nops; o++) {
        g.A[o] = ops[o].A; g.B[o] = ops[o].B;
        g.Kp[o] = ops[o].Kp;
        T += ops[o].Kp / 64;
    }
    g.nops = nops; g.totChunks = T;
    g.M = M; g.Nstore = Nstore; g.ldd = ldd;
    g.bias = bias; g.ps = ps; g.act = act;
    g.D = D; g.Dh = Dh;
}

extern "C" void kernel_launch(void* const* d_in, const int* in_sizes, int n_in,
                              void* d_out, int out_size)
{
    const float* x_window  = (const float*)d_in[0];
    const float* x_example = (const float*)d_in[1];
    const int*   e_near    = (const int*)d_in[2];
    const int*   e_close   = (const int*)d_in[3];
    const int*   e_refer   = (const int*)d_in[4];
    const float* W_win     = (const float*)d_in[5];
    const float* W_exp     = (const float*)d_in[6];
    const float* W_post    = (const float*)d_in[7];
    const float* Wl_near   = (const float*)d_in[9];
    const float* Wr_near   = (const float*)d_in[10];
    const float* b_near    = (const float*)d_in[11];
    const float* Wl_close  = (const float*)d_in[12];
    const float* Wr_close  = (const float*)d_in[13];
    const float* b_close   = (const float*)d_in[14];
    const float* Wl_refer  = (const float*)d_in[15];
    const float* Wr_refer  = (const float*)d_in[16];
    const float* b_refer   = (const float*)d_in[17];
    const float* w_pool    = (const float*)d_in[18];
    const float* W_lin     = (const float*)d_in[19];
    const float* b_lin     = (const float*)d_in[20];
    float* out = (float*)d_out;

    cudaFuncSetAttribute(gemm_mma_pair, cudaFuncAttributeMaxDynamicSharedMemorySize, GEMM_SMEM);
    cudaFuncSetAttribute(gemm512_pair, cudaFuncAttributeMaxDynamicSharedMemorySize, GEMM_SMEM2);

    float *score, *bsum, *lin0, *lin1;
    int *cnt, *off, *cur, *csrc;
    __half *wt, *big, *pt;
    __half *phw[2], *phe[2], *pa0, *pa1, *pa2;
    cudaGetSymbolAddress((void**)&score, g_score);
    cudaGetSymbolAddress((void**)&bsum, g_bsum);
    cudaGetSymbolAddress((void**)&lin0, g_lin0);
    cudaGetSymbolAddress((void**)&lin1, g_lin1);
    cudaGetSymbolAddress((void**)&cnt, g_cnt);
    cudaGetSymbolAddress((void**)&off, g_off);
    cudaGetSymbolAddress((void**)&cur, g_cur);
    cudaGetSymbolAddress((void**)&csrc, g_csrc);
    cudaGetSymbolAddress((void**)&wt, g_wt);
    cudaGetSymbolAddress((void**)&big, g_big);
    cudaGetSymbolAddress((void**)&pt, g_pt);
    cudaGetSymbolAddress((void**)&phw[0], g_phw0);
    cudaGetSymbolAddress((void**)&phw[1], g_phw1);
    cudaGetSymbolAddress((void**)&phe[0], g_phe0);
    cudaGetSymbolAddress((void**)&phe[1], g_phe1);
    cudaGetSymbolAddress((void**)&pa0, g_pa0);
    cudaGetSymbolAddress((void**)&pa1, g_pa1);
    cudaGetSymbolAddress((void**)&pa2, g_pa2);

    const unsigned edge_blocks = (EDG + 255) / 256;

    // --- batched weight conversion ---
    {
        ConvBatch cb;
        for (int l = 0; l < NLAYERS; l++) {
            size_t s = (size_t)l * HDIM * HDIM;
            cb.W1[l * 5 + 0] = Wl_near + s;  cb.W2[l * 5 + 0] = nullptr;      cb.dstoff[l * 5 + 0] = WOFF_WLN(l);
            cb.W1[l * 5 + 1] = Wl_refer + s; cb.W2[l * 5 + 1] = nullptr;      cb.dstoff[l * 5 + 1] = WOFF_WLR(l);
            cb.W1[l * 5 + 2] = Wr_near + s;  cb.W2[l * 5 + 2] = Wr_refer + s; cb.dstoff[l * 5 + 2] = WOFF_WSUM(l);
            cb.W1[l * 5 + 3] = Wl_close + s; cb.W2[l * 5 + 3] = nullptr;      cb.dstoff[l * 5 + 3] = WOFF_WLC(l);
            cb.W1[l * 5 + 4] = Wr_close + s; cb.W2[l * 5 + 4] = nullptr;      cb.dstoff[l * 5 + 4] = WOFF_WRC(l);
        }
        cb.W1[20] = W_post; cb.W2[20] = nullptr; cb.dstoff[20] = WOFF_POST;
        dim3 blk(32, 8);
        dim3 gB(HDIM / 32, HDIM / 32, NBATCH);
        conv_w_batch<<<gB, blk>>>(cb, wt);

        dim3 gWIN(KP_WIN / 32, HDIM / 32);
        conv_w<<<gWIN, blk>>>(W_win, KWIN, HDIM, KP_WIN, wt + WOFF_WIN);
        dim3 gEXP(128 / 32, HDIM / 32);
        conv_w<<<gEXP, blk>>>(W_exp, KEXP, HDIM, 128, wt + WOFF_EXP);
        dim3 gLIN(HDIM / 32, 128 / 32);
        conv_w<<<gLIN, blk>>>(W_lin, HDIM, NOUT, HDIM, wt + WOFF_LIN);
        bias_sum_all<<<(NLAYERS * HDIM + 255) / 256, 256>>>(b_near, b_refer, bsum);
    }

    // --- CSR build ---
    {
        EdgePtrs ep;
        ep.es[0] = e_near;  ep.ed[0] = e_near + EDG;
        ep.es[1] = e_refer; ep.ed[1] = e_refer + EDG;
        ep.es[2] = e_close; ep.ed[2] = e_close + EDG;
        zero_int<<<(3 * NWIN + 255) / 256, 256>>>(cnt, 3 * NWIN);
        dim3 ge(edge_blocks, 3);
        hist_all<<<ge, 256>>>(ep, cnt);
        scan_all<<<3, 1024>>>(cnt, off, cur);
        fill_all<<<ge, 256>>>(ep, cur, csrc);
    }

    // --- input projections (paired, 512-thread GEMM) ---
    {
        long long tot = (long long)MP * 128;
        conv_a<<<(unsigned)((tot + 255) / 256), 256>>>(x_example, NEX, KEXP, 128, tot, pa0);
        tot = (long long)MP * KP_WIN;
        conv_a<<<(unsigned)((tot + 255) / 256), 256>>>(x_window, NWIN, KWIN, KP_WIN, tot, big);

        GemmPair pr;
        OpDesc opw = { big, wt + WOFF_WIN, KP_WIN };
        OpDesc ope = { pa0, wt + WOFF_EXP, 128 };
        fill_args(pr.g[0], &opw, 1, NWIN, HDIM, HDIM, nullptr, 1.f, 1, nullptr, pt);
        fill_args(pr.g[1], &ope, 1, NEX, HDIM, HDIM, nullptr, 1.f, 1, nullptr, pa1);
        gemm512_pair<<<dim3(2, 235, 2), 512, GEMM_SMEM2>>>(pr);

        OpDesc opw2 = { pt, wt + WOFF_POST, HDIM };
        OpDesc ope2 = { pa1, wt + WOFF_POST, HDIM };
        fill_args(pr.g[0], &opw2, 1, NWIN, HDIM, HDIM, nullptr, 1.f, 1, nullptr, phw[0]);
        fill_args(pr.g[1], &ope2, 1, NEX, HDIM, HDIM, nullptr, 1.f, 1, nullptr, phe[0]);
        gemm512_pair<<<dim3(2, 235, 2), 512, GEMM_SMEM2>>>(pr);
    }

    // --- SAGE layers ---
    int curb = 0;
    for (int l = 0; l < NLAYERS; l++) {
        int nxt = curb ^ 1;
        GatherBatch gb;
        gb.src[0] = phw[curb];
        gb.src[1] = phe[curb];
        gb.src[2] = phe[curb];
        gb.off[0] = off + 0 * (NWIN + 1); gb.csrc[0] = csrc + 0 * (size_t)EDG; gb.ndst[0] = NWIN;
        gb.off[1] = off + 1 * (NWIN + 1); gb.csrc[1] = csrc + 1 * (size_t)EDG; gb.ndst[1] = NWIN;
        gb.off[2] = off + 2 * (NWIN + 1); gb.csrc[2] = csrc + 2 * (size_t)EDG; gb.ndst[2] = NEX;
        gb.o[0] = pa0; gb.o[1] = pa1; gb.o[2] = pa2;
        gather_all<<<dim3(MP / 2, 3), 128>>>(gb);

        GemmPair pr;
        OpDesc ops3[3] = {
            { pa0, wt + WOFF_WLN(l), HDIM },
            { pa1, wt + WOFF_WLR(l), HDIM },
            { phw[curb], wt + WOFF_WSUM(l), HDIM },
        };
        OpDesc ops2[2] = {
            { pa2, wt + WOFF_WLC(l), HDIM },
            { phe[curb], wt + WOFF_WRC(l), HDIM },
        };
        fill_args(pr.g[0], ops3, 3, NWIN, HDIM, HDIM, bsum + (size_t)l * HDIM, 0.5f, 1,
                  nullptr, phw[nxt]);
        fill_args(pr.g[1], ops2, 2, NEX, HDIM, HDIM, b_close + (size_t)l * HDIM, 1.f, 1,
                  nullptr, phe[nxt]);
        gemm512_pair<<<dim3(2, 235, 2), 512, GEMM_SMEM2>>>(pr);
        curb = nxt;
    }

    // --- score + low-dim projections (paired 128-wide GEMM) ---
    gemv_score<<<(NEX + 7) / 8, 256>>>(phe[curb], w_pool, score);
    {
        GemmPair pr;
        OpDesc opw = { phw[curb], wt + WOFF_LIN, HDIM };
        OpDesc ope = { phe[curb], wt + WOFF_LIN, HDIM };
        fill_args(pr.g[0], &opw, 1, NWIN, NOUT, NOUT, b_lin, 1.f, 0, lin0, nullptr);
        fill_args(pr.g[1], &ope, 1, NEX, NOUT, NOUT, nullptr, 1.f, 0, lin1, nullptr);
        gemm_mma_pair<<<dim3(1, 235, 2), 256, GEMM_SMEM>>>(pr);
    }

    // --- low-dim CSRA pooling -> out directly ---
    pool_small<<<NWIN, 128>>>(lin1, lin0, score,
                              off + 1 * (NWIN + 1), csrc + 1 * (size_t)EDG, out);
}

// round 15
// speedup vs baseline: 1.0488x; 1.0408x over previous
#include <cuda_runtime.h>
#include <cuda_fp16.h>
#include <float.h>
#include <math.h>
#include <stdint.h>

#define NWIN 30000
#define NEX  30000
#define EDG  480000
#define HDIM 512
#define NLAYERS 4
#define KWIN 1949
#define KEXP 100
#define NOUT 100
#define MP   30080
#define KP_WIN 1984

// ================= small fp32 scratch =================
__device__ float g_score[NEX];
__device__ float g_bsum[NLAYERS*HDIM];
__device__ __align__(256) float g_lin0[NWIN*NOUT];
__device__ __align__(256) float g_lin1[NEX*NOUT];

// ================= CSR scratch =================
__device__ int g_cnt[3*NWIN];
__device__ int g_off[3*(NWIN+1)];
__device__ int g_cur[3*NWIN];
__device__ int g_csrc[3*EDG];

// ================= fp16 weight buffers [N][Kp] (single plane) =================
#define WOFF_STEP   (HDIM*HDIM)
#define WOFF_LAYER  (5*WOFF_STEP)
#define WOFF_WLN(l) ((l)*WOFF_LAYER + 0*WOFF_STEP)
#define WOFF_WLR(l) ((l)*WOFF_LAYER + 1*WOFF_STEP)
#define WOFF_WSUM(l)((l)*WOFF_LAYER + 2*WOFF_STEP)
#define WOFF_WLC(l) ((l)*WOFF_LAYER + 3*WOFF_STEP)
#define WOFF_WRC(l) ((l)*WOFF_LAYER + 4*WOFF_STEP)
#define WOFF_POST   (NLAYERS*WOFF_LAYER)
#define WOFF_WIN    (WOFF_POST + WOFF_STEP)
#define WOFF_EXP    (WOFF_WIN + HDIM*KP_WIN)
#define WOFF_LIN    (WOFF_EXP + HDIM*128)
#define WTOTAL      (WOFF_LIN + 128*HDIM)
__device__ __align__(256) __half g_wt[WTOTAL];

// ================= fp16 activation plane buffers =================
__device__ __align__(256) __half g_big[(size_t)MP*KP_WIN];
__device__ __align__(256) __half g_pt[(size_t)MP*HDIM];
__device__ __align__(256) __half g_phw0[(size_t)MP*HDIM];
__device__ __align__(256) __half g_phw1[(size_t)MP*HDIM];
__device__ __align__(256) __half g_phe0[(size_t)MP*HDIM];
__device__ __align__(256) __half g_phe1[(size_t)MP*HDIM];
__device__ __align__(256) __half g_pa0[(size_t)MP*HDIM];
__device__ __align__(256) __half g_pa1[(size_t)MP*HDIM];
__device__ __align__(256) __half g_pa2[(size_t)MP*HDIM];

// ================= batched HxH weight conversion (transpose, fp16) ==========
#define NBATCH 21
struct ConvBatch {
    const float* W1[NBATCH];
    const float* W2[NBATCH];
    int dstoff[NBATCH];
};

__global__ void conv_w_batch(const __grid_constant__ ConvBatch cb,
                             __half* __restrict__ ob)
{
    __shared__ float t[32][33];
    int z = blockIdx.z;
    const float* W = cb.W1[z];
    const float* W2 = cb.W2[z];
    __half* o = ob + cb.dstoff[z];
    int k0 = blockIdx.x * 32, n0 = blockIdx.y * 32;
    int tx = threadIdx.x, ty = threadIdx.y;
#pragma unroll
    for (int i = 0; i < 4; i++) {
        int k = k0 + ty + i * 8, n = n0 + tx;
        float v = W[(size_t)k * HDIM + n];
        if (W2) v += W2[(size_t)k * HDIM + n];
        t[ty + i * 8][tx] = v;
    }
    __syncthreads();
#pragma unroll
    for (int i = 0; i < 4; i++) {
        int n = n0 + ty + i * 8, k = k0 + tx;
        o[(size_t)n * HDIM + k] = __float2half_rn(t[tx][ty + i * 8]);
    }
}

__global__ void conv_w(const float* __restrict__ W, int K, int N, int Kp,
                       __half* __restrict__ o)
{
    __shared__ float t[32][33];
    int k0 = blockIdx.x * 32, n0 = blockIdx.y * 32;
    int tx = threadIdx.x, ty = threadIdx.y;
#pragma unroll
    for (int i = 0; i < 4; i++) {
        int k = k0 + ty + i * 8, n = n0 + tx;
        float v = 0.f;
        if (k < K && n < N) v = W[(size_t)k * N + n];
        t[ty + i * 8][tx] = v;
    }
    __syncthreads();
#pragma unroll
    for (int i = 0; i < 4; i++) {
        int n = n0 + ty + i * 8, k = k0 + tx;
        o[(size_t)n * Kp + k] = __float2half_rn(t[tx][ty + i * 8]);
    }
}

__global__ void conv_a(const float* __restrict__ A, int M, int K, int Kp, long long total,
                       __half* __restrict__ o)
{
    long long i = (long long)blockIdx.x * blockDim.x + threadIdx.x;
    if (i >= total) return;
    int m = (int)(i / Kp);
    int k = (int)(i % Kp);
    float v = 0.f;
    if (m < M && k < K) v = A[(size_t)m * K + k];
    o[i] = __float2half_rn(v);
}

__global__ void bias_sum_all(const float* a, const float* b, float* o)
{
    int i = blockIdx.x * blockDim.x + threadIdx.x;
    if (i < NLAYERS * HDIM) o[i] = a[i] + b[i];
}

__global__ void zero_int(int* p, int n)
{
    int i = blockIdx.x * blockDim.x + threadIdx.x;
    if (i < n) p[i] = 0;
}

// ================= CSR build =================
struct EdgePtrs { const int* es[3]; const int* ed[3]; };

__global__ void hist_all(const __grid_constant__ EdgePtrs ep, int* __restrict__ cnt)
{
    int r = blockIdx.y;
    int e = blockIdx.x * blockDim.x + threadIdx.x;
    if (e < EDG) atomicAdd(&cnt[r * NWIN + ep.ed[r][e]], 1);
}

__global__ void scan_all(const int* __restrict__ cnt, int* __restrict__ off,
                         int* __restrict__ cur)
{
    __shared__ int s[1024];
    int r = blockIdx.x;
    const int* c = cnt + r * NWIN;
    int* of = off + r * (NWIN + 1);
    int* cu = cur + r * NWIN;
    int t = threadIdx.x;
    int chunk = (NWIN + 1023) >> 10;
    int b = t * chunk, e = min(b + chunk, NWIN);
    int sum = 0;
    for (int i = b; i < e; i++) sum += c[i];
    s[t] = sum;
    __syncthreads();
    for (int d = 1; d < 1024; d <<= 1) {
        int v = (t >= d) ? s[t - d] : 0;
        __syncthreads();
        s[t] += v;
        __syncthreads();
    }
    int run = (t == 0) ? 0 : s[t - 1];
    for (int i = b; i < e; i++) {
        of[i] = run; cu[i] = run; run += c[i];
    }
    if (t == 0) of[NWIN] = s[1023];
}

__global__ void fill_all(const __grid_constant__ EdgePtrs ep, int* __restrict__ cur,
                         int* __restrict__ csrc)
{
    int r = blockIdx.y;
    int e = blockIdx.x * blockDim.x + threadIdx.x;
    if (e < EDG) {
        int p = atomicAdd(&cur[r * NWIN + ep.ed[r][e]], 1);
        csrc[(size_t)r * EDG + p] = ep.es[r][e];
    }
}

// ================= fused 3-relation gather-mean (fp16, 128 thr / 2 rows) ===========
struct GatherBatch {
    const __half *src[3];
    const int *off[3], *csrc[3];
    int ndst[3];
    __half *o[3];
};

__device__ __forceinline__ void acc8h(float* acc, uint4 q)
{
    const __half2* h2 = (const __half2*)&q;
#pragma unroll
    for (int j = 0; j < 4; j++) {
        float2 f = __half22float2(h2[j]);
        acc[j * 2 + 0] += f.x;
        acc[j * 2 + 1] += f.y;
    }
}

__global__ void gather_all(const __grid_constant__ GatherBatch gb)
{
    int r = blockIdx.y;
    int t = threadIdx.x;
    int d = blockIdx.x * 2 + (t >> 6);
    int c = (t & 63) * 8;
    const __half* src = gb.src[r];

    float acc[8];
#pragma unroll
    for (int j = 0; j < 8; j++) acc[j] = 0.f;
    int deg = 0;
    if (d < gb.ndst[r]) {
        const int* off = gb.off[r];
        const int* cs = gb.csrc[r];
        int s0 = off[d], s1 = off[d + 1];
        deg = s1 - s0;
        int e = s0;
        for (; e + 4 <= s1; e += 4) {
            int i0 = cs[e], i1 = cs[e + 1], i2 = cs[e + 2], i3 = cs[e + 3];
            uint4 q0 = *(const uint4*)(src + (size_t)i0 * HDIM + c);
            uint4 q1 = *(const uint4*)(src + (size_t)i1 * HDIM + c);
            uint4 q2 = *(const uint4*)(src + (size_t)i2 * HDIM + c);
            uint4 q3 = *(const uint4*)(src + (size_t)i3 * HDIM + c);
            acc8h(acc, q0); acc8h(acc, q1); acc8h(acc, q2); acc8h(acc, q3);
        }
        for (; e < s1; e++) {
            uint4 q = *(const uint4*)(src + (size_t)cs[e] * HDIM + c);
            acc8h(acc, q);
        }
    }
    float inv = 1.f / (float)max(deg, 1);
    __half2 o2[4];
#pragma unroll
    for (int j = 0; j < 4; j++)
        o2[j] = __floats2half2_rn(acc[j * 2] * inv, acc[j * 2 + 1] * inv);
    *(uint4*)(gb.o[r] + (size_t)d * HDIM + c) = *(uint4*)o2;
}

// ================= low-dim CSRA pooling =================
__global__ void pool_small(const float* __restrict__ helin,
                           const float* __restrict__ hwlin,
                           const float* __restrict__ score,
                           const int* __restrict__ off, const int* __restrict__ csrc,
                           float* __restrict__ out)
{
    __shared__ float red[128];
    __shared__ float wts[128];
    __shared__ int   idx[128];
    int d = blockIdx.x;
    int t = threadIdx.x;
    if (d >= NWIN) return;
    int s0 = off[d], s1 = off[d + 1];

    float m = -FLT_MAX;
    for (int e = s0 + t; e < s1; e += 128) m = fmaxf(m, score[csrc[e]]);
    red[t] = m; __syncthreads();
    for (int w = 64; w; w >>= 1) {
        if (t < w) red[t] = fmaxf(red[t], red[t + w]);
        __syncthreads();
    }
    float smax = red[0];
    __syncthreads();
    float z = 0.f;
    for (int e = s0 + t; e < s1; e += 128) z += expf(score[csrc[e]] - smax);
    red[t] = z; __syncthreads();
    for (int w = 64; w; w >>= 1) {
        if (t < w) red[t] += red[t + w];
        __syncthreads();
    }
    float invz = 1.f / fmaxf(red[0], 1e-12f);
    __syncthreads();

    float acc = 0.f;
    for (int base = s0; base < s1; base += 128) {
        int e = base + t;
        if (e < s1) {
            int si = csrc[e];
            idx[t] = si;
            wts[t] = expf(score[si] - smax) * invz;
        }
        __syncthreads();
        int cnt = min(128, s1 - base);
        if (t < NOUT) {
            for (int j = 0; j < cnt; j++)
                acc += wts[j] * helin[(size_t)idx[j] * NOUT + t];
        }
        __syncthreads();
    }
    if (t < NOUT)
        out[(size_t)d * NOUT + t] = hwlin[(size_t)d * NOUT + t] + 0.5f * acc;
}

__global__ void gemv_score(const __half* __restrict__ he,
                           const float* __restrict__ w, float* __restrict__ sc)
{
    int row = blockIdx.x * 8 + (threadIdx.x >> 5);
    if (row >= NEX) return;
    int lane = threadIdx.x & 31;
    float s = 0.f;
#pragma unroll
    for (int k = lane * 4; k < HDIM; k += 128) {
        __half2 a = *(const __half2*)(he + (size_t)row * HDIM + k);
        __half2 b = *(const __half2*)(he + (size_t)row * HDIM + k + 2);
        float2 fa = __half22float2(a), fb = __half22float2(b);
        s += fa.x * w[k] + fa.y * w[k + 1] + fb.x * w[k + 2] + fb.y * w[k + 3];
    }
#pragma unroll
    for (int o = 16; o; o >>= 1) s += __shfl_down_sync(0xFFFFFFFFu, s, o);
    if (lane == 0) sc[row] = s;
}

// ================= GEMM common (fp16 single-pass) =================
struct GemmArgs {
    const __half *A[3], *B[3];
    int Kp[3];
    int nops, totChunks;
    int M, Nstore, ldd;
    const float* bias;
    float ps;
    int act;
    float* D;
    __half* Dh;
};
struct GemmPair { GemmArgs g[2]; };

__device__ __forceinline__ uint32_t smem_u32(const void* p) {
    uint32_t a;
    asm("{ .reg .u64 t; cvta.to.shared.u64 t, %1; cvt.u32.u64 %0, t; }" : "=r"(a) : "l"(p));
    return a;
}
__device__ __forceinline__ void cp16(uint32_t dst, const void* src) {
    asm volatile("cp.async.cg.shared.global [%0], [%1], 16;" :: "r"(dst), "l"(src));
}
__device__ __forceinline__ void cp_commit() { asm volatile("cp.async.commit_group;"); }
__device__ __forceinline__ void cp_wait0() { asm volatile("cp.async.wait_group 0;"); }
__device__ __forceinline__ void cp_wait1() { asm volatile("cp.async.wait_group 1;"); }

__device__ __forceinline__ void ldm_x4(uint32_t* r, uint32_t addr) {
    asm volatile("ldmatrix.sync.aligned.m8n8.x4.shared.b16 {%0,%1,%2,%3}, [%4];"
                 : "=r"(r[0]), "=r"(r[1]), "=r"(r[2]), "=r"(r[3]) : "r"(addr));
}
__device__ __forceinline__ void mma16816(float* c, const uint32_t* a, const uint32_t* b) {
    asm volatile("mma.sync.aligned.m16n8k16.row.col.f32.f16.f16.f32 "
                 "{%0,%1,%2,%3},{%4,%5,%6,%7},{%8,%9},{%0,%1,%2,%3};"
                 : "+f"(c[0]), "+f"(c[1]), "+f"(c[2]), "+f"(c[3])
                 : "r"(a[0]), "r"(a[1]), "r"(a[2]), "r"(a[3]), "r"(b[0]), "r"(b[1]));
}

__device__ __forceinline__ void map_oc(const GemmArgs& g, int t, int& o, int& c) {
    o = 0;
    int rem = t;
    while (o < g.nops - 1 && rem >= (g.Kp[o] >> 6)) { rem -= (g.Kp[o] >> 6); o++; }
    c = rem;
}

__device__ __forceinline__ void epi_frag(const GemmArgs& g, const float* a4,
                                         int row0, int col)
{
    if (col >= g.Nstore) return;
    float b0 = 0.f, b1 = 0.f;
    if (g.bias) {
        b0 = g.bias[col];
        if (col + 1 < g.Nstore) b1 = g.bias[col + 1];
    }
#pragma unroll
    for (int rr = 0; rr < 2; rr++) {
        int r = row0 + rr * 8;
        if (r >= g.M) continue;
        float v0 = (a4[rr * 2 + 0] + b0) * g.ps;
        float v1 = (a4[rr * 2 + 1] + b1) * g.ps;
        if (g.act) {
            v0 = v0 > 0.f ? v0 : 0.2f * v0;
            v1 = v1 > 0.f ? v1 : 0.2f * v1;
        }
        if (g.D) {
            float* dp = g.D + (size_t)r * g.ldd + col;
            if (col + 1 < g.Nstore) *(float2*)dp = make_float2(v0, v1);
            else *dp = v0;
        }
        if (g.Dh) {
            *(__half2*)(g.Dh + (size_t)r * HDIM + col) = __floats2half2_rn(v0, v1);
        }
    }
}

// ================= 512-thread 128x256 GEMM (BK=64) =================
#define STAGE2      49152      // A 16K, B 32K
#define GEMM_SMEM2  (2 * STAGE2)

__device__ __forceinline__ void load_stage512(const GemmArgs& g, int t, uint32_t sb,
                                              int tid, int m0, int n0)
{
    int o, c;
    map_oc(g, t, o, c);
    const int Kp = g.Kp[o];
    const int k0 = c << 6;
    {
        const __half* a_ = g.A[o] + (size_t)m0 * Kp + k0;
#pragma unroll
        for (int it = 0; it < 2; it++) {
            int idx = it * 512 + tid;
            int r = idx >> 3;
            int j = idx & 7;
            uint32_t sw = r * 128 + ((j ^ (r & 7)) << 4);
            cp16(sb + sw, a_ + (size_t)r * Kp + j * 8);
        }
    }
    {
        const __half* b_ = g.B[o] + (size_t)n0 * Kp + k0;
#pragma unroll
        for (int it = 0; it < 4; it++) {
            int idx = it * 512 + tid;
            int r = idx >> 3;
            int j = idx & 7;
            uint32_t sw = r * 128 + ((j ^ (r & 7)) << 4);
            cp16(sb + 16384 + sw, b_ + (size_t)r * Kp + j * 8);
        }
    }
    cp_commit();
}

__device__ __forceinline__ void gemm_body512(const GemmArgs& g, char* smem)
{
    const uint32_t sbase = smem_u32(smem);
    const int tid = threadIdx.x;
    const int lane = tid & 31;
    const int warp = tid >> 5;
    const int wm = warp >> 2;
    const int wn = warp & 3;
    const int m0 = blockIdx.y * 128;
    const int n0 = blockIdx.x * 256;

    float acc[2][8][4];
#pragma unroll
    for (int i = 0; i < 2; i++)
#pragma unroll
        for (int j = 0; j < 8; j++)
#pragma unroll
            for (int q = 0; q < 4; q++) acc[i][j][q] = 0.f;

    const int sx = lane & 7;
    const int arow = (lane & 7) + ((lane >> 3) & 1) * 8;
    const int khia = (lane >> 4) & 1;
    const int brow = (lane & 7) + ((lane >> 4) & 1) * 8;
    const int khib = (lane >> 3) & 1;

    const int T = g.totChunks;
    load_stage512(g, 0, sbase, tid, m0, n0);

    for (int t = 0; t < T; t++) {
        if (t + 1 < T) {
            load_stage512(g, t + 1, sbase + ((t + 1) & 1) * STAGE2, tid, m0, n0);
            cp_wait1();
        } else {
            cp_wait0();
        }
        __syncthreads();

        const uint32_t Ab = sbase + (t & 1) * STAGE2;
        const uint32_t Bb = Ab + 16384;

#pragma unroll
        for (int ks = 0; ks < 4; ks++) {
            const uint32_t colA = (uint32_t)(((ks * 2 + khia) ^ sx) << 4);
            const uint32_t colB = (uint32_t)(((ks * 2 + khib) ^ sx) << 4);
            uint32_t ah[2][4];
#pragma unroll
            for (int mt = 0; mt < 2; mt++) {
                int row = wm * 32 + mt * 16 + arow;
                ldm_x4(ah[mt], Ab + row * 128 + colA);
            }
#pragma unroll
            for (int half = 0; half < 2; half++) {
                uint32_t bh[2][4];
#pragma unroll
                for (int np = 0; np < 2; np++) {
                    int row = wn * 64 + half * 32 + np * 16 + brow;
                    ldm_x4(bh[np], Bb + row * 128 + colB);
                }
#pragma unroll
                for (int mt = 0; mt < 2; mt++) {
#pragma unroll
                    for (int nt = 0; nt < 4; nt++) {
                        const uint32_t* bf = &bh[nt >> 1][(nt & 1) * 2];
                        mma16816(acc[mt][half * 4 + nt], ah[mt], bf);
                    }
                }
            }
        }
        __syncthreads();
    }

#pragma unroll
    for (int mt = 0; mt < 2; mt++) {
        int row0 = m0 + wm * 32 + mt * 16 + (lane >> 2);
#pragma unroll
        for (int nt = 0; nt < 8; nt++) {
            int col = n0 + wn * 64 + nt * 8 + (lane & 3) * 2;
            epi_frag(g, acc[mt][nt], row0, col);
        }
    }
}

__global__ __launch_bounds__(512, 1) void gemm512_pair(const __grid_constant__ GemmPair p)
{
    extern __shared__ __align__(128) char smem[];
    gemm_body512(p.g[blockIdx.z], smem);
}

// ================= 256-thread 128x128 GEMM =================
#define STAGE_BYTES 32768      // A 16K, B 16K
#define GEMM_SMEM   (2 * STAGE_BYTES)

__device__ __forceinline__ void load_stage(const GemmArgs& g, int t, uint32_t sb,
                                           int tid, int m0, int n0)
{
    int o, c;
    map_oc(g, t, o, c);
    const int Kp = g.Kp[o];
    const int k0 = c << 6;
    {
        const __half* a_ = g.A[o] + (size_t)m0 * Kp + k0;
#pragma unroll
        for (int it = 0; it < 4; it++) {
            int idx = it * 256 + tid;
            int r = idx >> 3;
            int j = idx & 7;
            uint32_t sw = r * 128 + ((j ^ (r & 7)) << 4);
            cp16(sb + sw, a_ + (size_t)r * Kp + j * 8);
        }
    }
    {
        const __half* b_ = g.B[o] + (size_t)n0 * Kp + k0;
#pragma unroll
        for (int it = 0; it < 4; it++) {
            int idx = it * 256 + tid;
            int r = idx >> 3;
            int j = idx & 7;
            uint32_t sw = r * 128 + ((j ^ (r & 7)) << 4);
            cp16(sb + 16384 + sw, b_ + (size_t)r * Kp + j * 8);
        }
    }
    cp_commit();
}

__device__ __forceinline__ void gemm_body128(const GemmArgs& g, char* smem)
{
    const uint32_t sbase = smem_u32(smem);
    const int tid = threadIdx.x;
    const int lane = tid & 31;
    const int warp = tid >> 5;
    const int wm = warp >> 2;
    const int wn = warp & 3;
    const int m0 = blockIdx.y * 128;
    const int n0 = blockIdx.x * 128;

    float acc[4][4][4];
#pragma unroll
    for (int i = 0; i < 4; i++)
#pragma unroll
        for (int j = 0; j < 4; j++)
#pragma unroll
            for (int q = 0; q < 4; q++) acc[i][j][q] = 0.f;

    const int sx = lane & 7;
    const int arow = (lane & 7) + ((lane >> 3) & 1) * 8;
    const int khia = (lane >> 4) & 1;
    const int brow = (lane & 7) + ((lane >> 4) & 1) * 8;
    const int khib = (lane >> 3) & 1;

    const int T = g.totChunks;
    load_stage(g, 0, sbase, tid, m0, n0);

    for (int t = 0; t < T; t++) {
        if (t + 1 < T) {
            load_stage(g, t + 1, sbase + ((t + 1) & 1) * STAGE_BYTES, tid, m0, n0);
            cp_wait1();
        } else {
            cp_wait0();
        }
        __syncthreads();

        const uint32_t Ab = sbase + (t & 1) * STAGE_BYTES;
        const uint32_t Bb = Ab + 16384;

#pragma unroll
        for (int ks = 0; ks < 4; ks++) {
            uint32_t ah[4][4], bh[2][4];
            const uint32_t colA = (uint32_t)(((ks * 2 + khia) ^ sx) << 4);
            const uint32_t colB = (uint32_t)(((ks * 2 + khib) ^ sx) << 4);
#pragma unroll
            for (int mt = 0; mt < 4; mt++) {
                int row = wm * 64 + mt * 16 + arow;
                ldm_x4(ah[mt], Ab + row * 128 + colA);
            }
#pragma unroll
            for (int np = 0; np < 2; np++) {
                int row = wn * 32 + np * 16 + brow;
                ldm_x4(bh[np], Bb + row * 128 + colB);
            }
#pragma unroll
            for (int mt = 0; mt < 4; mt++) {
#pragma unroll
                for (int nt = 0; nt < 4; nt++) {
                    const uint32_t* bf = &bh[nt >> 1][(nt & 1) * 2];
                    mma16816(acc[mt][nt], ah[mt], bf);
                }
            }
        }
        __syncthreads();
    }

#pragma unroll
    for (int mt = 0; mt < 4; mt++) {
        int row0 = m0 + wm * 64 + mt * 16 + (lane >> 2);
#pragma unroll
        for (int nt = 0; nt < 4; nt++) {
            int col = n0 + wn * 32 + nt * 8 + (lane & 3) * 2;
            epi_frag(g, acc[mt][nt], row0, col);
        }
    }
}

__global__ __launch_bounds__(256, 1) void gemm_mma_pair(const __grid_constant__ GemmPair p)
{
    extern __shared__ __align__(128) char smem[];
    gemm_body128(p.g[blockIdx.z], smem);
}

// ================= host orchestration =================
struct OpDesc {
    const __half *A, *B;
    int Kp;
};

static void fill_args(GemmArgs& g, const OpDesc* ops, int nops, int M, int Nstore,
                      int ldd, const float* bias, float ps, int act,
                      float* D, __half* Dh)
{
    int T = 0;
    for (int o = 0; o < nops; o++) {
        g.A[o] = ops[o].A; g.B[o] = ops[o].B;
        g.Kp[o] = ops[o].Kp;
        T += ops[o].Kp / 64;
    }
    g.nops = nops; g.totChunks = T;
    g.M = M; g.Nstore = Nstore; g.ldd = ldd;
    g.bias = bias; g.ps = ps; g.act = act;
    g.D = D; g.Dh = Dh;
}

extern "C" void kernel_launch(void* const* d_in, const int* in_sizes, int n_in,
                              void* d_out, int out_size)
{
    const float* x_window  = (const float*)d_in[0];
    const float* x_example = (const float*)d_in[1];
    const int*   e_near    = (const int*)d_in[2];
    const int*   e_close   = (const int*)d_in[3];
    const int*   e_refer   = (const int*)d_in[4];
    const float* W_win     = (const float*)d_in[5];
    const float* W_exp     = (const float*)d_in[6];
    const float* W_post    = (const float*)d_in[7];
    const float* Wl_near   = (const float*)d_in[9];
    const float* Wr_near   = (const float*)d_in[10];
    const float* b_near    = (const float*)d_in[11];
    const float* Wl_close  = (const float*)d_in[12];
    const float* Wr_close  = (const float*)d_in[13];
    const float* b_close   = (const float*)d_in[14];
    const float* Wl_refer  = (const float*)d_in[15];
    const float* Wr_refer  = (const float*)d_in[16];
    const float* b_refer   = (const float*)d_in[17];
    const float* w_pool    = (const float*)d_in[18];
    const float* W_lin     = (const float*)d_in[19];
    const float* b_lin     = (const float*)d_in[20];
    float* out = (float*)d_out;

    cudaFuncSetAttribute(gemm_mma_pair, cudaFuncAttributeMaxDynamicSharedMemorySize, GEMM_SMEM);
    cudaFuncSetAttribute(gemm512_pair, cudaFuncAttributeMaxDynamicSharedMemorySize, GEMM_SMEM2);

    float *score, *bsum, *lin0, *lin1;
    int *cnt, *off, *cur, *csrc;
    __half *wt, *big, *pt;
    __half *phw[2], *phe[2], *pa0, *pa1, *pa2;
    cudaGetSymbolAddress((void**)&score, g_score);
    cudaGetSymbolAddress((void**)&bsum, g_bsum);
    cudaGetSymbolAddress((void**)&lin0, g_lin0);
    cudaGetSymbolAddress((void**)&lin1, g_lin1);
    cudaGetSymbolAddress((void**)&cnt, g_cnt);
    cudaGetSymbolAddress((void**)&off, g_off);
    cudaGetSymbolAddress((void**)&cur, g_cur);
    cudaGetSymbolAddress((void**)&csrc, g_csrc);
    cudaGetSymbolAddress((void**)&wt, g_wt);
    cudaGetSymbolAddress((void**)&big, g_big);
    cudaGetSymbolAddress((void**)&pt, g_pt);
    cudaGetSymbolAddress((void**)&phw[0], g_phw0);
    cudaGetSymbolAddress((void**)&phw[1], g_phw1);
    cudaGetSymbolAddress((void**)&phe[0], g_phe0);
    cudaGetSymbolAddress((void**)&phe[1], g_phe1);
    cudaGetSymbolAddress((void**)&pa0, g_pa0);
    cudaGetSymbolAddress((void**)&pa1, g_pa1);
    cudaGetSymbolAddress((void**)&pa2, g_pa2);

    const unsigned edge_blocks = (EDG + 255) / 256;

    // --- batched weight conversion ---
    {
        ConvBatch cb;
        for (int l = 0; l < NLAYERS; l++) {
            size_t s = (size_t)l * HDIM * HDIM;
            cb.W1[l * 5 + 0] = Wl_near + s;  cb.W2[l * 5 + 0] = nullptr;      cb.dstoff[l * 5 + 0] = WOFF_WLN(l);
            cb.W1[l * 5 + 1] = Wl_refer + s; cb.W2[l * 5 + 1] = nullptr;      cb.dstoff[l * 5 + 1] = WOFF_WLR(l);
            cb.W1[l * 5 + 2] = Wr_near + s;  cb.W2[l * 5 + 2] = Wr_refer + s; cb.dstoff[l * 5 + 2] = WOFF_WSUM(l);
            cb.W1[l * 5 + 3] = Wl_close + s; cb.W2[l * 5 + 3] = nullptr;      cb.dstoff[l * 5 + 3] = WOFF_WLC(l);
            cb.W1[l * 5 + 4] = Wr_close + s; cb.W2[l * 5 + 4] = nullptr;      cb.dstoff[l * 5 + 4] = WOFF_WRC(l);
        }
        cb.W1[20] = W_post; cb.W2[20] = nullptr; cb.dstoff[20] = WOFF_POST;
        dim3 blk(32, 8);
        dim3 gB(HDIM / 32, HDIM / 32, NBATCH);
        conv_w_batch<<<gB, blk>>>(cb, wt);

        dim3 gWIN(KP_WIN / 32, HDIM / 32);
        conv_w<<<gWIN, blk>>>(W_win, KWIN, HDIM, KP_WIN, wt + WOFF_WIN);
        dim3 gEXP(128 / 32, HDIM / 32);
        conv_w<<<gEXP, blk>>>(W_exp, KEXP, HDIM, 128, wt + WOFF_EXP);
        dim3 gLIN(HDIM / 32, 128 / 32);
        conv_w<<<gLIN, blk>>>(W_lin, HDIM, NOUT, HDIM, wt + WOFF_LIN);
        bias_sum_all<<<(NLAYERS * HDIM + 255) / 256, 256>>>(b_near, b_refer, bsum);
    }

    // --- CSR build ---
    {
        EdgePtrs ep;
        ep.es[0] = e_near;  ep.ed[0] = e_near + EDG;
        ep.es[1] = e_refer; ep.ed[1] = e_refer + EDG;
        ep.es[2] = e_close; ep.ed[2] = e_close + EDG;
        zero_int<<<(3 * NWIN + 255) / 256, 256>>>(cnt, 3 * NWIN);
        dim3 ge(edge_blocks, 3);
        hist_all<<<ge, 256>>>(ep, cnt);
        scan_all<<<3, 1024>>>(cnt, off, cur);
        fill_all<<<ge, 256>>>(ep, cur, csrc);
    }

    // --- input projections (paired, 512-thread GEMM) ---
    {
        long long tot = (long long)MP * 128;
        conv_a<<<(unsigned)((tot + 255) / 256), 256>>>(x_example, NEX, KEXP, 128, tot, pa0);
        tot = (long long)MP * KP_WIN;
        conv_a<<<(unsigned)((tot + 255) / 256), 256>>>(x_window, NWIN, KWIN, KP_WIN, tot, big);

        GemmPair pr;
        OpDesc opw = { big, wt + WOFF_WIN, KP_WIN };
        OpDesc ope = { pa0, wt + WOFF_EXP, 128 };
        fill_args(pr.g[0], &opw, 1, NWIN, HDIM, HDIM, nullptr, 1.f, 1, nullptr, pt);
        fill_args(pr.g[1], &ope, 1, NEX, HDIM, HDIM, nullptr, 1.f, 1, nullptr, pa1);
        gemm512_pair<<<dim3(2, 235, 2), 512, GEMM_SMEM2>>>(pr);

        OpDesc opw2 = { pt, wt + WOFF_POST, HDIM };
        OpDesc ope2 = { pa1, wt + WOFF_POST, HDIM };
        fill_args(pr.g[0], &opw2, 1, NWIN, HDIM, HDIM, nullptr, 1.f, 1, nullptr, phw[0]);
        fill_args(pr.g[1], &ope2, 1, NEX, HDIM, HDIM, nullptr, 1.f, 1, nullptr, phe[0]);
        gemm512_pair<<<dim3(2, 235, 2), 512, GEMM_SMEM2>>>(pr);
    }

    // --- SAGE layers ---
    int curb = 0;
    for (int l = 0; l < NLAYERS; l++) {
        int nxt = curb ^ 1;
        GatherBatch gb;
        gb.src[0] = phw[curb];
        gb.src[1] = phe[curb];
        gb.src[2] = phe[curb];
        gb.off[0] = off + 0 * (NWIN + 1); gb.csrc[0] = csrc + 0 * (size_t)EDG; gb.ndst[0] = NWIN;
        gb.off[1] = off + 1 * (NWIN + 1); gb.csrc[1] = csrc + 1 * (size_t)EDG; gb.ndst[1] = NWIN;
        gb.off[2] = off + 2 * (NWIN + 1); gb.csrc[2] = csrc + 2 * (size_t)EDG; gb.ndst[2] = NEX;
        gb.o[0] = pa0; gb.o[1] = pa1; gb.o[2] = pa2;
        gather_all<<<dim3(MP / 2, 3), 128>>>(gb);

        GemmPair pr;
        OpDesc ops3[3] = {
            { pa0, wt + WOFF_WLN(l), HDIM },
            { pa1, wt + WOFF_WLR(l), HDIM },
            { phw[curb], wt + WOFF_WSUM(l), HDIM },
        };
        OpDesc ops2[2] = {
            { pa2, wt + WOFF_WLC(l), HDIM },
            { phe[curb], wt + WOFF_WRC(l), HDIM },
        };
        fill_args(pr.g[0], ops3, 3, NWIN, HDIM, HDIM, bsum + (size_t)l * HDIM, 0.5f, 1,
                  nullptr, phw[nxt]);
        fill_args(pr.g[1], ops2, 2, NEX, HDIM, HDIM, b_close + (size_t)l * HDIM, 1.f, 1,
                  nullptr, phe[nxt]);
        gemm512_pair<<<dim3(2, 235, 2), 512, GEMM_SMEM2>>>(pr);
        curb = nxt;
    }

    // --- score + low-dim projections (paired 128-wide GEMM) ---
    gemv_score<<<(NEX + 7) / 8, 256>>>(phe[curb], w_pool, score);
    {
        GemmPair pr;
        OpDesc opw = { phw[curb], wt + WOFF_LIN, HDIM };
        OpDesc ope = { phe[curb], wt + WOFF_LIN, HDIM };
        fill_args(pr.g[0], &opw, 1, NWIN, NOUT, NOUT, b_lin, 1.f, 0, lin0, nullptr);
        fill_args(pr.g[1], &ope, 1, NEX, NOUT, NOUT, nullptr, 1.f, 0, lin1, nullptr);
        gemm_mma_pair<<<dim3(1, 235, 2), 256, GEMM_SMEM>>>(pr);
    }

    // --- low-dim CSRA pooling -> out directly ---
    pool_small<<<NWIN, 128>>>(lin1, lin0, score,
                              off + 1 * (NWIN + 1), csrc + 1 * (size_t)EDG, out);
}

// round 16
// speedup vs baseline: 1.0596x; 1.0104x over previous
#include <cuda_runtime.h>
#include <cuda_fp16.h>
#include <float.h>
#include <math.h>
#include <stdint.h>

#define NWIN 30000
#define NEX  30000
#define EDG  480000
#define HDIM 512
#define NLAYERS 4
#define KWIN 1949
#define KEXP 100
#define NOUT 100
#define LD1  104            // padded row stride for lin buffers (101 cols stored)
#define MP   30080
#define KP_WIN 1984

// ================= small fp32 scratch =================
__device__ float g_score[NEX];
__device__ float g_bsum[NLAYERS*HDIM];
__device__ float g_blin[LD1];
__device__ __align__(256) float g_lin0[(size_t)NWIN*LD1];
__device__ __align__(256) float g_lin1[(size_t)NEX*LD1];

// ================= CSR scratch =================
__device__ int g_cnt[3*NWIN];
__device__ int g_off[3*(NWIN+1)];
__device__ int g_cur[3*NWIN];
__device__ int g_csrc[3*EDG];

// ================= fp16 weight buffers [N][Kp] (single plane) =================
#define WOFF_STEP   (HDIM*HDIM)
#define WOFF_LAYER  (5*WOFF_STEP)
#define WOFF_WLN(l) ((l)*WOFF_LAYER + 0*WOFF_STEP)
#define WOFF_WLR(l) ((l)*WOFF_LAYER + 1*WOFF_STEP)
#define WOFF_WSUM(l)((l)*WOFF_LAYER + 2*WOFF_STEP)
#define WOFF_WLC(l) ((l)*WOFF_LAYER + 3*WOFF_STEP)
#define WOFF_WRC(l) ((l)*WOFF_LAYER + 4*WOFF_STEP)
#define WOFF_POST   (NLAYERS*WOFF_LAYER)
#define WOFF_WIN    (WOFF_POST + WOFF_STEP)
#define WOFF_EXP    (WOFF_WIN + HDIM*KP_WIN)
#define WOFF_LIN    (WOFF_EXP + HDIM*128)
#define WTOTAL      (WOFF_LIN + 128*HDIM)
__device__ __align__(256) __half g_wt[WTOTAL];

// ================= fp16 activation plane buffers =================
__device__ __align__(256) __half g_big[(size_t)MP*KP_WIN];
__device__ __align__(256) __half g_pt[(size_t)MP*HDIM];
__device__ __align__(256) __half g_phw0[(size_t)MP*HDIM];
__device__ __align__(256) __half g_phw1[(size_t)MP*HDIM];
__device__ __align__(256) __half g_phe0[(size_t)MP*HDIM];
__device__ __align__(256) __half g_phe1[(size_t)MP*HDIM];
__device__ __align__(256) __half g_pa0[(size_t)MP*HDIM];
__device__ __align__(256) __half g_pa1[(size_t)MP*HDIM];
__device__ __align__(256) __half g_pa2[(size_t)MP*HDIM];

// ================= batched HxH weight conversion (transpose, fp16) ==========
#define NBATCH 21
struct ConvBatch {
    const float* W1[NBATCH];
    const float* W2[NBATCH];
    int dstoff[NBATCH];
};

__global__ void conv_w_batch(const __grid_constant__ ConvBatch cb,
                             __half* __restrict__ ob)
{
    __shared__ float t[32][33];
    int z = blockIdx.z;
    const float* W = cb.W1[z];
    const float* W2 = cb.W2[z];
    __half* o = ob + cb.dstoff[z];
    int k0 = blockIdx.x * 32, n0 = blockIdx.y * 32;
    int tx = threadIdx.x, ty = threadIdx.y;
#pragma unroll
    for (int i = 0; i < 4; i++) {
        int k = k0 + ty + i * 8, n = n0 + tx;
        float v = W[(size_t)k * HDIM + n];
        if (W2) v += W2[(size_t)k * HDIM + n];
        t[ty + i * 8][tx] = v;
    }
    __syncthreads();
#pragma unroll
    for (int i = 0; i < 4; i++) {
        int n = n0 + ty + i * 8, k = k0 + tx;
        o[(size_t)n * HDIM + k] = __float2half_rn(t[tx][ty + i * 8]);
    }
}

__global__ void conv_w(const float* __restrict__ W, int K, int N, int Kp,
                       __half* __restrict__ o)
{
    __shared__ float t[32][33];
    int k0 = blockIdx.x * 32, n0 = blockIdx.y * 32;
    int tx = threadIdx.x, ty = threadIdx.y;
#pragma unroll
    for (int i = 0; i < 4; i++) {
        int k = k0 + ty + i * 8, n = n0 + tx;
        float v = 0.f;
        if (k < K && n < N) v = W[(size_t)k * N + n];
        t[ty + i * 8][tx] = v;
    }
    __syncthreads();
#pragma unroll
    for (int i = 0; i < 4; i++) {
        int n = n0 + ty + i * 8, k = k0 + tx;
        o[(size_t)n * Kp + k] = __float2half_rn(t[tx][ty + i * 8]);
    }
}

__global__ void conv_a(const float* __restrict__ A, int M, int K, int Kp, long long total,
                       __half* __restrict__ o)
{
    long long i = (long long)blockIdx.x * blockDim.x + threadIdx.x;
    if (i >= total) return;
    int m = (int)(i / Kp);
    int k = (int)(i % Kp);
    float v = 0.f;
    if (m < M && k < K) v = A[(size_t)m * K + k];
    o[i] = __float2half_rn(v);
}

// append w_pool as row 100 of W_lin buffer; pad bias to LD1
__global__ void append_wpool(const float* __restrict__ wp, __half* __restrict__ wlin,
                             const float* __restrict__ blin, float* __restrict__ bpad)
{
    int k = threadIdx.x + blockIdx.x * blockDim.x;
    if (k < HDIM) wlin[(size_t)100 * HDIM + k] = __float2half_rn(wp[k]);
    if (k < LD1) bpad[k] = (k < NOUT) ? blin[k] : 0.f;
}

__global__ void bias_sum_all(const float* a, const float* b, float* o)
{
    int i = blockIdx.x * blockDim.x + threadIdx.x;
    if (i < NLAYERS * HDIM) o[i] = a[i] + b[i];
}

__global__ void zero_int(int* p, int n)
{
    int i = blockIdx.x * blockDim.x + threadIdx.x;
    if (i < n) p[i] = 0;
}

// compact score = lin1[:,100]
__global__ void extract_score(const float* __restrict__ lin1, float* __restrict__ sc)
{
    int i = blockIdx.x * blockDim.x + threadIdx.x;
    if (i < NEX) sc[i] = lin1[(size_t)i * LD1 + 100];
}

// ================= CSR build =================
struct EdgePtrs { const int* es[3]; const int* ed[3]; };

__global__ void hist_all(const __grid_constant__ EdgePtrs ep, int* __restrict__ cnt)
{
    int r = blockIdx.y;
    int e = blockIdx.x * blockDim.x + threadIdx.x;
    if (e < EDG) atomicAdd(&cnt[r * NWIN + ep.ed[r][e]], 1);
}

__global__ void scan_all(const int* __restrict__ cnt, int* __restrict__ off,
                         int* __restrict__ cur)
{
    __shared__ int s[1024];
    int r = blockIdx.x;
    const int* c = cnt + r * NWIN;
    int* of = off + r * (NWIN + 1);
    int* cu = cur + r * NWIN;
    int t = threadIdx.x;
    int chunk = (NWIN + 1023) >> 10;
    int b = t * chunk, e = min(b + chunk, NWIN);
    int sum = 0;
    for (int i = b; i < e; i++) sum += c[i];
    s[t] = sum;
    __syncthreads();
    for (int d = 1; d < 1024; d <<= 1) {
        int v = (t >= d) ? s[t - d] : 0;
        __syncthreads();
        s[t] += v;
        __syncthreads();
    }
    int run = (t == 0) ? 0 : s[t - 1];
    for (int i = b; i < e; i++) {
        of[i] = run; cu[i] = run; run += c[i];
    }
    if (t == 0) of[NWIN] = s[1023];
}

__global__ void fill_all(const __grid_constant__ EdgePtrs ep, int* __restrict__ cur,
                         int* __restrict__ csrc)
{
    int r = blockIdx.y;
    int e = blockIdx.x * blockDim.x + threadIdx.x;
    if (e < EDG) {
        int p = atomicAdd(&cur[r * NWIN + ep.ed[r][e]], 1);
        csrc[(size_t)r * EDG + p] = ep.es[r][e];
    }
}

// ================= fused 3-relation gather-mean (fp16, 128 thr / 2 rows) ===========
struct GatherBatch {
    const __half *src[3];
    const int *off[3], *csrc[3];
    int ndst[3];
    __half *o[3];
};

__device__ __forceinline__ void acc8h(float* acc, uint4 q)
{
    const __half2* h2 = (const __half2*)&q;
#pragma unroll
    for (int j = 0; j < 4; j++) {
        float2 f = __half22float2(h2[j]);
        acc[j * 2 + 0] += f.x;
        acc[j * 2 + 1] += f.y;
    }
}

__global__ void gather_all(const __grid_constant__ GatherBatch gb)
{
    int r = blockIdx.y;
    int t = threadIdx.x;
    int d = blockIdx.x * 2 + (t >> 6);
    int c = (t & 63) * 8;
    const __half* src = gb.src[r];

    float acc[8];
#pragma unroll
    for (int j = 0; j < 8; j++) acc[j] = 0.f;
    int deg = 0;
    if (d < gb.ndst[r]) {
        const int* off = gb.off[r];
        const int* cs = gb.csrc[r];
        int s0 = off[d], s1 = off[d + 1];
        deg = s1 - s0;
        int e = s0;
        for (; e + 4 <= s1; e += 4) {
            int i0 = cs[e], i1 = cs[e + 1], i2 = cs[e + 2], i3 = cs[e + 3];
            uint4 q0 = __ldg((const uint4*)(src + (size_t)i0 * HDIM + c));
            uint4 q1 = __ldg((const uint4*)(src + (size_t)i1 * HDIM + c));
            uint4 q2 = __ldg((const uint4*)(src + (size_t)i2 * HDIM + c));
            uint4 q3 = __ldg((const uint4*)(src + (size_t)i3 * HDIM + c));
            acc8h(acc, q0); acc8h(acc, q1); acc8h(acc, q2); acc8h(acc, q3);
        }
        for (; e < s1; e++) {
            uint4 q = __ldg((const uint4*)(src + (size_t)cs[e] * HDIM + c));
            acc8h(acc, q);
        }
    }
    float inv = 1.f / (float)max(deg, 1);
    __half2 o2[4];
#pragma unroll
    for (int j = 0; j < 4; j++)
        o2[j] = __floats2half2_rn(acc[j * 2] * inv, acc[j * 2 + 1] * inv);
    *(uint4*)(gb.o[r] + (size_t)d * HDIM + c) = *(uint4*)o2;
}

// ================= low-dim CSRA pooling (helin/hwlin stride LD1) =================
__global__ void pool_small(const float* __restrict__ helin,
                           const float* __restrict__ hwlin,
                           const float* __restrict__ score,
                           const int* __restrict__ off, const int* __restrict__ csrc,
                           float* __restrict__ out)
{
    __shared__ float red[128];
    __shared__ float wts[128];
    __shared__ int   idx[128];
    int d = blockIdx.x;
    int t = threadIdx.x;
    if (d >= NWIN) return;
    int s0 = off[d], s1 = off[d + 1];

    float m = -FLT_MAX;
    for (int e = s0 + t; e < s1; e += 128) m = fmaxf(m, score[csrc[e]]);
    red[t] = m; __syncthreads();
    for (int w = 64; w; w >>= 1) {
        if (t < w) red[t] = fmaxf(red[t], red[t + w]);
        __syncthreads();
    }
    float smax = red[0];
    __syncthreads();
    float z = 0.f;
    for (int e = s0 + t; e < s1; e += 128) z += expf(score[csrc[e]] - smax);
    red[t] = z; __syncthreads();
    for (int w = 64; w; w >>= 1) {
        if (t < w) red[t] += red[t + w];
        __syncthreads();
    }
    float invz = 1.f / fmaxf(red[0], 1e-12f);
    __syncthreads();

    float acc = 0.f;
    for (int base = s0; base < s1; base += 128) {
        int e = base + t;
        if (e < s1) {
            int si = csrc[e];
            idx[t] = si;
            wts[t] = expf(score[si] - smax) * invz;
        }
        __syncthreads();
        int cnt = min(128, s1 - base);
        if (t < NOUT) {
            for (int j = 0; j < cnt; j++)
                acc += wts[j] * helin[(size_t)idx[j] * LD1 + t];
        }
        __syncthreads();
    }
    if (t < NOUT)
        out[(size_t)d * NOUT + t] = hwlin[(size_t)d * LD1 + t] + 0.5f * acc;
}

// ================= GEMM common (fp16 single-pass) =================
struct GemmArgs {
    const __half *A[3], *B[3];
    int Kp[3];
    int nops, totChunks;
    int M, Nstore, ldd;
    const float* bias;
    float ps;
    int act;
    float* D;
    __half* Dh;
};
struct GemmPair { GemmArgs g[2]; };

__device__ __forceinline__ uint32_t smem_u32(const void* p) {
    uint32_t a;
    asm("{ .reg .u64 t; cvta.to.shared.u64 t, %1; cvt.u32.u64 %0, t; }" : "=r"(a) : "l"(p));
    return a;
}
__device__ __forceinline__ void cp16(uint32_t dst, const void* src) {
    asm volatile("cp.async.cg.shared.global [%0], [%1], 16;" :: "r"(dst), "l"(src));
}
__device__ __forceinline__ void cp_commit() { asm volatile("cp.async.commit_group;"); }
__device__ __forceinline__ void cp_wait0() { asm volatile("cp.async.wait_group 0;"); }
__device__ __forceinline__ void cp_wait1() { asm volatile("cp.async.wait_group 1;"); }

__device__ __forceinline__ void ldm_x4(uint32_t* r, uint32_t addr) {
    asm volatile("ldmatrix.sync.aligned.m8n8.x4.shared.b16 {%0,%1,%2,%3}, [%4];"
                 : "=r"(r[0]), "=r"(r[1]), "=r"(r[2]), "=r"(r[3]) : "r"(addr));
}
__device__ __forceinline__ void mma16816(float* c, const uint32_t* a, const uint32_t* b) {
    asm volatile("mma.sync.aligned.m16n8k16.row.col.f32.f16.f16.f32 "
                 "{%0,%1,%2,%3},{%4,%5,%6,%7},{%8,%9},{%0,%1,%2,%3};"
                 : "+f"(c[0]), "+f"(c[1]), "+f"(c[2]), "+f"(c[3])
                 : "r"(a[0]), "r"(a[1]), "r"(a[2]), "r"(a[3]), "r"(b[0]), "r"(b[1]));
}

__device__ __forceinline__ void map_oc(const GemmArgs& g, int t, int& o, int& c) {
    o = 0;
    int rem = t;
    while (o < g.nops - 1 && rem >= (g.Kp[o] >> 6)) { rem -= (g.Kp[o] >> 6); o++; }
    c = rem;
}

__device__ __forceinline__ void epi_frag(const GemmArgs& g, const float* a4,
                                         int row0, int col)
{
    if (col >= g.Nstore) return;
    float b0 = 0.f, b1 = 0.f;
    if (g.bias) {
        b0 = g.bias[col];
        if (col + 1 < g.Nstore) b1 = g.bias[col + 1];
    }
#pragma unroll
    for (int rr = 0; rr < 2; rr++) {
        int r = row0 + rr * 8;
        if (r >= g.M) continue;
        float v0 = (a4[rr * 2 + 0] + b0) * g.ps;
        float v1 = (a4[rr * 2 + 1] + b1) * g.ps;
        if (g.act) {
            v0 = v0 > 0.f ? v0 : 0.2f * v0;
            v1 = v1 > 0.f ? v1 : 0.2f * v1;
        }
        if (g.D) {
            float* dp = g.D + (size_t)r * g.ldd + col;
            if (col + 1 < g.Nstore) *(float2*)dp = make_float2(v0, v1);
            else *dp = v0;
        }
        if (g.Dh) {
            *(__half2*)(g.Dh + (size_t)r * HDIM + col) = __floats2half2_rn(v0, v1);
        }
    }
}

// ================= 512-thread 128x256 GEMM (BK=64) =================
#define STAGE2      49152      // A 16K, B 32K
#define GEMM_SMEM2  (2 * STAGE2)

__device__ __forceinline__ void load_stage512(const GemmArgs& g, int t, uint32_t sb,
                                              int tid, int m0, int n0)
{
    int o, c;
    map_oc(g, t, o, c);
    const int Kp = g.Kp[o];
    const int k0 = c << 6;
    {
        const __half* a_ = g.A[o] + (size_t)m0 * Kp + k0;
#pragma unroll
        for (int it = 0; it < 2; it++) {
            int idx = it * 512 + tid;
            int r = idx >> 3;
            int j = idx & 7;
            uint32_t sw = r * 128 + ((j ^ (r & 7)) << 4);
            cp16(sb + sw, a_ + (size_t)r * Kp + j * 8);
        }
    }
    {
        const __half* b_ = g.B[o] + (size_t)n0 * Kp + k0;
#pragma unroll
        for (int it = 0; it < 4; it++) {
            int idx = it * 512 + tid;
            int r = idx >> 3;
            int j = idx & 7;
            uint32_t sw = r * 128 + ((j ^ (r & 7)) << 4);
            cp16(sb + 16384 + sw, b_ + (size_t)r * Kp + j * 8);
        }
    }
    cp_commit();
}

__device__ __forceinline__ void gemm_body512(const GemmArgs& g, char* smem)
{
    const uint32_t sbase = smem_u32(smem);
    const int tid = threadIdx.x;
    const int lane = tid & 31;
    const int warp = tid >> 5;
    const int wm = warp >> 2;
    const int wn = warp & 3;
    const int m0 = blockIdx.y * 128;
    const int n0 = blockIdx.x * 256;

    float acc[2][8][4];
#pragma unroll
    for (int i = 0; i < 2; i++)
#pragma unroll
        for (int j = 0; j < 8; j++)
#pragma unroll
            for (int q = 0; q < 4; q++) acc[i][j][q] = 0.f;

    const int sx = lane & 7;
    const int arow = (lane & 7) + ((lane >> 3) & 1) * 8;
    const int khia = (lane >> 4) & 1;
    const int brow = (lane & 7) + ((lane >> 4) & 1) * 8;
    const int khib = (lane >> 3) & 1;

    const int T = g.totChunks;
    load_stage512(g, 0, sbase, tid, m0, n0);

    for (int t = 0; t < T; t++) {
        if (t + 1 < T) {
            load_stage512(g, t + 1, sbase + ((t + 1) & 1) * STAGE2, tid, m0, n0);
            cp_wait1();
        } else {
            cp_wait0();
        }
        __syncthreads();

        const uint32_t Ab = sbase + (t & 1) * STAGE2;
        const uint32_t Bb = Ab + 16384;

#pragma unroll
        for (int ks = 0; ks < 4; ks++) {
            const uint32_t colA = (uint32_t)(((ks * 2 + khia) ^ sx) << 4);
            const uint32_t colB = (uint32_t)(((ks * 2 + khib) ^ sx) << 4);
            uint32_t ah[2][4];
#pragma unroll
            for (int mt = 0; mt < 2; mt++) {
                int row = wm * 32 + mt * 16 + arow;
                ldm_x4(ah[mt], Ab + row * 128 + colA);
            }
#pragma unroll
            for (int half = 0; half < 2; half++) {
                uint32_t bh[2][4];
#pragma unroll
                for (int np = 0; np < 2; np++) {
                    int row = wn * 64 + half * 32 + np * 16 + brow;
                    ldm_x4(bh[np], Bb + row * 128 + colB);
                }
#pragma unroll
                for (int mt = 0; mt < 2; mt++) {
#pragma unroll
                    for (int nt = 0; nt < 4; nt++) {
                        const uint32_t* bf = &bh[nt >> 1][(nt & 1) * 2];
                        mma16816(acc[mt][half * 4 + nt], ah[mt], bf);
                    }
                }
            }
        }
        __syncthreads();
    }

#pragma unroll
    for (int mt = 0; mt < 2; mt++) {
        int row0 = m0 + wm * 32 + mt * 16 + (lane >> 2);
#pragma unroll
        for (int nt = 0; nt < 8; nt++) {
            int col = n0 + wn * 64 + nt * 8 + (lane & 3) * 2;
            epi_frag(g, acc[mt][nt], row0, col);
        }
    }
}

__global__ __launch_bounds__(512, 1) void gemm512_pair(const __grid_constant__ GemmPair p)
{
    extern __shared__ __align__(128) char smem[];
    gemm_body512(p.g[blockIdx.z], smem);
}

// ================= 256-thread 128x128 GEMM =================
#define STAGE_BYTES 32768      // A 16K, B 16K
#define GEMM_SMEM   (2 * STAGE_BYTES)

__device__ __forceinline__ void load_stage(const GemmArgs& g, int t, uint32_t sb,
                                           int tid, int m0, int n0)
{
    int o, c;
    map_oc(g, t, o, c);
    const int Kp = g.Kp[o];
    const int k0 = c << 6;
    {
        const __half* a_ = g.A[o] + (size_t)m0 * Kp + k0;
#pragma unroll
        for (int it = 0; it < 4; it++) {
            int idx = it * 256 + tid;
            int r = idx >> 3;
            int j = idx & 7;
            uint32_t sw = r * 128 + ((j ^ (r & 7)) << 4);
            cp16(sb + sw, a_ + (size_t)r * Kp + j * 8);
        }
    }
    {
        const __half* b_ = g.B[o] + (size_t)n0 * Kp + k0;
#pragma unroll
        for (int it = 0; it < 4; it++) {
            int idx = it * 256 + tid;
            int r = idx >> 3;
            int j = idx & 7;
            uint32_t sw = r * 128 + ((j ^ (r & 7)) << 4);
            cp16(sb + 16384 + sw, b_ + (size_t)r * Kp + j * 8);
        }
    }
    cp_commit();
}

__device__ __forceinline__ void gemm_body128(const GemmArgs& g, char* smem)
{
    const uint32_t sbase = smem_u32(smem);
    const int tid = threadIdx.x;
    const int lane = tid & 31;
    const int warp = tid >> 5;
    const int wm = warp >> 2;
    const int wn = warp & 3;
    const int m0 = blockIdx.y * 128;
    const int n0 = blockIdx.x * 128;

    float acc[4][4][4];
#pragma unroll
    for (int i = 0; i < 4; i++)
#pragma unroll
        for (int j = 0; j < 4; j++)
#pragma unroll
            for (int q = 0; q < 4; q++) acc[i][j][q] = 0.f;

    const int sx = lane & 7;
    const int arow = (lane & 7) + ((lane >> 3) & 1) * 8;
    const int khia = (lane >> 4) & 1;
    const int brow = (lane & 7) + ((lane >> 4) & 1) * 8;
    const int khib = (lane >> 3) & 1;

    const int T = g.totChunks;
    load_stage(g, 0, sbase, tid, m0, n0);

    for (int t = 0; t < T; t++) {
        if (t + 1 < T) {
            load_stage(g, t + 1, sbase + ((t + 1) & 1) * STAGE_BYTES, tid, m0, n0);
            cp_wait1();
        } else {
            cp_wait0();
        }
        __syncthreads();

        const uint32_t Ab = sbase + (t & 1) * STAGE_BYTES;
        const uint32_t Bb = Ab + 16384;

#pragma unroll
        for (int ks = 0; ks < 4; ks++) {
            uint32_t ah[4][4], bh[2][4];
            const uint32_t colA = (uint32_t)(((ks * 2 + khia) ^ sx) << 4);
            const uint32_t colB = (uint32_t)(((ks * 2 + khib) ^ sx) << 4);
#pragma unroll
            for (int mt = 0; mt < 4; mt++) {
                int row = wm * 64 + mt * 16 + arow;
                ldm_x4(ah[mt], Ab + row * 128 + colA);
            }
#pragma unroll
            for (int np = 0; np < 2; np++) {
                int row = wn * 32 + np * 16 + brow;
                ldm_x4(bh[np], Bb + row * 128 + colB);
            }
#pragma unroll
            for (int mt = 0; mt < 4; mt++) {
#pragma unroll
                for (int nt = 0; nt < 4; nt++) {
                    const uint32_t* bf = &bh[nt >> 1][(nt & 1) * 2];
                    mma16816(acc[mt][nt], ah[mt], bf);
                }
            }
        }
        __syncthreads();
    }

#pragma unroll
    for (int mt = 0; mt < 4; mt++) {
        int row0 = m0 + wm * 64 + mt * 16 + (lane >> 2);
#pragma unroll
        for (int nt = 0; nt < 4; nt++) {
            int col = n0 + wn * 32 + nt * 8 + (lane & 3) * 2;
            epi_frag(g, acc[mt][nt], row0, col);
        }
    }
}

__global__ __launch_bounds__(256, 1) void gemm_mma_pair(const __grid_constant__ GemmPair p)
{
    extern __shared__ __align__(128) char smem[];
    gemm_body128(p.g[blockIdx.z], smem);
}

// ================= host orchestration =================
struct OpDesc {
    const __half *A, *B;
    int Kp;
};

static void fill_args(GemmArgs& g, const OpDesc* ops, int nops, int M, int Nstore,
                      int ldd, const float* bias, float ps, int act,
                      float* D, __half* Dh)
{
    int T = 0;
    for (int o = 0; o < nops; o++) {
        g.A[o] = ops[o].A; g.B[o] = ops[o].B;
        g.Kp[o] = ops[o].Kp;
        T += ops[o].Kp / 64;
    }
    g.nops = nops; g.totChunks = T;
    g.M = M; g.Nstore = Nstore; g.ldd = ldd;
    g.bias = bias; g.ps = ps; g.act = act;
    g.D = D; g.Dh = Dh;
}

extern "C" void kernel_launch(void* const* d_in, const int* in_sizes, int n_in,
                              void* d_out, int out_size)
{
    const float* x_window  = (const float*)d_in[0];
    const float* x_example = (const float*)d_in[1];
    const int*   e_near    = (const int*)d_in[2];
    const int*   e_close   = (const int*)d_in[3];
    const int*   e_refer   = (const int*)d_in[4];
    const float* W_win     = (const float*)d_in[5];
    const float* W_exp     = (const float*)d_in[6];
    const float* W_post    = (const float*)d_in[7];
    const float* Wl_near   = (const float*)d_in[9];
    const float* Wr_near   = (const float*)d_in[10];
    const float* b_near    = (const float*)d_in[11];
    const float* Wl_close  = (const float*)d_in[12];
    const float* Wr_close  = (const float*)d_in[13];
    const float* b_close   = (const float*)d_in[14];
    const float* Wl_refer  = (const float*)d_in[15];
    const float* Wr_refer  = (const float*)d_in[16];
    const float* b_refer   = (const float*)d_in[17];
    const float* w_pool    = (const float*)d_in[18];
    const float* W_lin     = (const float*)d_in[19];
    const float* b_lin     = (const float*)d_in[20];
    float* out = (float*)d_out;

    cudaFuncSetAttribute(gemm_mma_pair, cudaFuncAttributeMaxDynamicSharedMemorySize, GEMM_SMEM);
    cudaFuncSetAttribute(gemm512_pair, cudaFuncAttributeMaxDynamicSharedMemorySize, GEMM_SMEM2);

    float *score, *bsum, *blin, *lin0, *lin1;
    int *cnt, *off, *cur, *csrc;
    __half *wt, *big, *pt;
    __half *phw[2], *phe[2], *pa0, *pa1, *pa2;
    cudaGetSymbolAddress((void**)&score, g_score);
    cudaGetSymbolAddress((void**)&bsum, g_bsum);
    cudaGetSymbolAddress((void**)&blin, g_blin);
    cudaGetSymbolAddress((void**)&lin0, g_lin0);
    cudaGetSymbolAddress((void**)&lin1, g_lin1);
    cudaGetSymbolAddress((void**)&cnt, g_cnt);
    cudaGetSymbolAddress((void**)&off, g_off);
    cudaGetSymbolAddress((void**)&cur, g_cur);
    cudaGetSymbolAddress((void**)&csrc, g_csrc);
    cudaGetSymbolAddress((void**)&wt, g_wt);
    cudaGetSymbolAddress((void**)&big, g_big);
    cudaGetSymbolAddress((void**)&pt, g_pt);
    cudaGetSymbolAddress((void**)&phw[0], g_phw0);
    cudaGetSymbolAddress((void**)&phw[1], g_phw1);
    cudaGetSymbolAddress((void**)&phe[0], g_phe0);
    cudaGetSymbolAddress((void**)&phe[1], g_phe1);
    cudaGetSymbolAddress((void**)&pa0, g_pa0);
    cudaGetSymbolAddress((void**)&pa1, g_pa1);
    cudaGetSymbolAddress((void**)&pa2, g_pa2);

    const unsigned edge_blocks = (EDG + 255) / 256;

    // --- batched weight conversion ---
    {
        ConvBatch cb;
        for (int l = 0; l < NLAYERS; l++) {
            size_t s = (size_t)l * HDIM * HDIM;
            cb.W1[l * 5 + 0] = Wl_near + s;  cb.W2[l * 5 + 0] = nullptr;      cb.dstoff[l * 5 + 0] = WOFF_WLN(l);
            cb.W1[l * 5 + 1] = Wl_refer + s; cb.W2[l * 5 + 1] = nullptr;      cb.dstoff[l * 5 + 1] = WOFF_WLR(l);
            cb.W1[l * 5 + 2] = Wr_near + s;  cb.W2[l * 5 + 2] = Wr_refer + s; cb.dstoff[l * 5 + 2] = WOFF_WSUM(l);
            cb.W1[l * 5 + 3] = Wl_close + s; cb.W2[l * 5 + 3] = nullptr;      cb.dstoff[l * 5 + 3] = WOFF_WLC(l);
            cb.W1[l * 5 + 4] = Wr_close + s; cb.W2[l * 5 + 4] = nullptr;      cb.dstoff[l * 5 + 4] = WOFF_WRC(l);
        }
        cb.W1[20] = W_post; cb.W2[20] = nullptr; cb.dstoff[20] = WOFF_POST;
        dim3 blk(32, 8);
        dim3 gB(HDIM / 32, HDIM / 32, NBATCH);
        conv_w_batch<<<gB, blk>>>(cb, wt);

        dim3 gWIN(KP_WIN / 32, HDIM / 32);
        conv_w<<<gWIN, blk>>>(W_win, KWIN, HDIM, KP_WIN, wt + WOFF_WIN);
        dim3 gEXP(128 / 32, HDIM / 32);
        conv_w<<<gEXP, blk>>>(W_exp, KEXP, HDIM, 128, wt + WOFF_EXP);
        dim3 gLIN(HDIM / 32, 128 / 32);
        conv_w<<<gLIN, blk>>>(W_lin, HDIM, NOUT, HDIM, wt + WOFF_LIN);
        // fold w_pool into row 100 of the W_lin buffer; pad bias
        append_wpool<<<2, 256>>>(w_pool, wt + WOFF_LIN, b_lin, blin);
        bias_sum_all<<<(NLAYERS * HDIM + 255) / 256, 256>>>(b_near, b_refer, bsum);
    }

    // --- CSR build ---
    {
        EdgePtrs ep;
        ep.es[0] = e_near;  ep.ed[0] = e_near + EDG;
        ep.es[1] = e_refer; ep.ed[1] = e_refer + EDG;
        ep.es[2] = e_close; ep.ed[2] = e_close + EDG;
        zero_int<<<(3 * NWIN + 255) / 256, 256>>>(cnt, 3 * NWIN);
        dim3 ge(edge_blocks, 3);
        hist_all<<<ge, 256>>>(ep, cnt);
        scan_all<<<3, 1024>>>(cnt, off, cur);
        fill_all<<<ge, 256>>>(ep, cur, csrc);
    }

    // --- input projections (paired, 512-thread GEMM) ---
    {
        long long tot = (long long)MP * 128;
        conv_a<<<(unsigned)((tot + 255) / 256), 256>>>(x_example, NEX, KEXP, 128, tot, pa0);
        tot = (long long)MP * KP_WIN;
        conv_a<<<(unsigned)((tot + 255) / 256), 256>>>(x_window, NWIN, KWIN, KP_WIN, tot, big);

        GemmPair pr;
        OpDesc opw = { big, wt + WOFF_WIN, KP_WIN };
        OpDesc ope = { pa0, wt + WOFF_EXP, 128 };
        fill_args(pr.g[0], &opw, 1, NWIN, HDIM, HDIM, nullptr, 1.f, 1, nullptr, pt);
        fill_args(pr.g[1], &ope, 1, NEX, HDIM, HDIM, nullptr, 1.f, 1, nullptr, pa1);
        gemm512_pair<<<dim3(2, 235, 2), 512, GEMM_SMEM2>>>(pr);

        OpDesc opw2 = { pt, wt + WOFF_POST, HDIM };
        OpDesc ope2 = { pa1, wt + WOFF_POST, HDIM };
        fill_args(pr.g[0], &opw2, 1, NWIN, HDIM, HDIM, nullptr, 1.f, 1, nullptr, phw[0]);
        fill_args(pr.g[1], &ope2, 1, NEX, HDIM, HDIM, nullptr, 1.f, 1, nullptr, phe[0]);
        gemm512_pair<<<dim3(2, 235, 2), 512, GEMM_SMEM2>>>(pr);
    }

    // --- SAGE layers ---
    int curb = 0;
    for (int l = 0; l < NLAYERS; l++) {
        int nxt = curb ^ 1;
        GatherBatch gb;
        gb.src[0] = phw[curb];
        gb.src[1] = phe[curb];
        gb.src[2] = phe[curb];
        gb.off[0] = off + 0 * (NWIN + 1); gb.csrc[0] = csrc + 0 * (size_t)EDG; gb.ndst[0] = NWIN;
        gb.off[1] = off + 1 * (NWIN + 1); gb.csrc[1] = csrc + 1 * (size_t)EDG; gb.ndst[1] = NWIN;
        gb.off[2] = off + 2 * (NWIN + 1); gb.csrc[2] = csrc + 2 * (size_t)EDG; gb.ndst[2] = NEX;
        gb.o[0] = pa0; gb.o[1] = pa1; gb.o[2] = pa2;
        gather_all<<<dim3(MP / 2, 3), 128>>>(gb);

        GemmPair pr;
        OpDesc ops3[3] = {
            { pa0, wt + WOFF_WLN(l), HDIM },
            { pa1, wt + WOFF_WLR(l), HDIM },
            { phw[curb], wt + WOFF_WSUM(l), HDIM },
        };
        OpDesc ops2[2] = {
            { pa2, wt + WOFF_WLC(l), HDIM },
            { phe[curb], wt + WOFF_WRC(l), HDIM },
        };
        fill_args(pr.g[0], ops3, 3, NWIN, HDIM, HDIM, bsum + (size_t)l * HDIM, 0.5f, 1,
                  nullptr, phw[nxt]);
        fill_args(pr.g[1], ops2, 2, NEX, HDIM, HDIM, b_close + (size_t)l * HDIM, 1.f, 1,
                  nullptr, phe[nxt]);
        gemm512_pair<<<dim3(2, 235, 2), 512, GEMM_SMEM2>>>(pr);
        curb = nxt;
    }

    // --- low-dim projections (score folded in as column 100) ---
    {
        GemmPair pr;
        OpDesc opw = { phw[curb], wt + WOFF_LIN, HDIM };
        OpDesc ope = { phe[curb], wt + WOFF_LIN, HDIM };
        fill_args(pr.g[0], &opw, 1, NWIN, NOUT + 1, LD1, blin, 1.f, 0, lin0, nullptr);
        fill_args(pr.g[1], &ope, 1, NEX, NOUT + 1, LD1, nullptr, 1.f, 0, lin1, nullptr);
        gemm_mma_pair<<<dim3(1, 235, 2), 256, GEMM_SMEM>>>(pr);
    }

    // --- compact score column, then low-dim CSRA pooling -> out ---
    extract_score<<<(NEX + 255) / 256, 256>>>(lin1, score);
    pool_small<<<NWIN, 128>>>(lin1, lin0, score,
                              off + 1 * (NWIN + 1), csrc + 1 * (size_t)EDG, out);
}